// round 6
// baseline (speedup 1.0000x reference)
#include <cuda_runtime.h>
#include <cuda_bf16.h>
#include <math.h>
#include <stdint.h>

typedef __nv_bfloat16 bf16;

#define Bq 8
#define Tq 1024
#define Dq 4096
#define Hq 4
#define HSq 1024
#define BT 8192
#define FFq 20480

// ----------------------------- scratch --------------------------------------
__device__ bf16 g_srcH[(size_t)BT*Dq], g_srcL[(size_t)BT*Dq];
__device__ bf16 g_attH[(size_t)BT*HSq], g_attL[(size_t)BT*HSq];
__device__ bf16 g_WqTH[(size_t)Hq*HSq*Dq], g_WqTL[(size_t)Hq*HSq*Dq];
__device__ bf16 g_WkTH[(size_t)Hq*HSq*Dq], g_WkTL[(size_t)Hq*HSq*Dq];
__device__ bf16 g_WvTH[(size_t)Hq*HSq*Dq], g_WvTL[(size_t)Hq*HSq*Dq];
__device__ bf16 g_qH[(size_t)Hq*BT*HSq], g_qL[(size_t)Hq*BT*HSq];
__device__ bf16 g_kH[(size_t)Hq*BT*HSq], g_kL[(size_t)Hq*BT*HSq];
__device__ float g_v[(size_t)Hq*BT*HSq];
__device__ bf16 g_vTH[(size_t)Hq*BT*HSq], g_vTL[(size_t)Hq*BT*HSq];
__device__ float g_w[(size_t)Hq*Bq*Tq*Tq];
__device__ bf16 g_aH[(size_t)Hq*Bq*Tq*Tq], g_aL[(size_t)Hq*Bq*Tq*Tq];
__device__ float g_ocat[(size_t)BT*Dq];
__device__ float g_srcA[(size_t)BT*Dq];
__device__ bf16 g_srcAH[(size_t)BT*Dq], g_srcAL[(size_t)BT*Dq];
__device__ bf16 g_dWpTH[(size_t)Hq*Dq*HSq], g_dWpTL[(size_t)Hq*Dq*HSq];
__device__ bf16 g_wpH[(size_t)Hq*BT*Dq], g_wpL[(size_t)Hq*BT*Dq];
__device__ bf16 g_o2H[(size_t)BT*Dq], g_o2L[(size_t)BT*Dq];
__device__ bf16 g_dWoTH[(size_t)Dq*Dq], g_dWoTL[(size_t)Dq*Dq];
__device__ float g_o3[(size_t)BT*Dq];
__device__ float g_trgf[(size_t)BT*Dq];
__device__ bf16 g_ln2H[(size_t)BT*Dq], g_ln2L[(size_t)BT*Dq];
__device__ bf16 g_fW1TH[(size_t)FFq*Dq], g_fW1TL[(size_t)FFq*Dq];
__device__ bf16 g_h1H[(size_t)BT*FFq], g_h1L[(size_t)BT*FFq];
__device__ bf16 g_fW2TH[(size_t)Dq*FFq], g_fW2TL[(size_t)Dq*FFq];
__device__ float g_ff[(size_t)BT*Dq];

// ----------------------------- helpers --------------------------------------
__device__ __forceinline__ uint32_t smem_u32(const void* p) {
    uint32_t a;
    asm("{ .reg .u64 t; cvta.to.shared.u64 t, %1; cvt.u32.u64 %0, t; }" : "=r"(a) : "l"(p));
    return a;
}
#define CPA16(dst, src) asm volatile("cp.async.cg.shared.global [%0], [%1], 16;" :: "r"((uint32_t)(dst)), "l"(src) : "memory")
#define CP_COMMIT()     asm volatile("cp.async.commit_group;" ::: "memory")
#define CP_WAIT1()      asm volatile("cp.async.wait_group 1;" ::: "memory")
#define LDSM4(r, a) asm volatile("ldmatrix.sync.aligned.m8n8.x4.shared.b16 {%0,%1,%2,%3}, [%4];" \
    : "=r"((r)[0]), "=r"((r)[1]), "=r"((r)[2]), "=r"((r)[3]) : "r"(a))
__device__ __forceinline__ void mma16816(float* d, const uint32_t* a, uint32_t b0, uint32_t b1) {
    asm volatile("mma.sync.aligned.m16n8k16.row.col.f32.bf16.bf16.f32 "
        "{%0,%1,%2,%3}, {%4,%5,%6,%7}, {%8,%9}, {%0,%1,%2,%3};"
        : "+f"(d[0]), "+f"(d[1]), "+f"(d[2]), "+f"(d[3])
        : "r"(a[0]), "r"(a[1]), "r"(a[2]), "r"(a[3]), "r"(b0), "r"(b1));
}
__device__ __forceinline__ float gelu_exact(float x) { return 0.5f*x*(1.0f+erff(x*0.70710678118654752440f)); }
__device__ __forceinline__ void split_bf(float x, bf16& h, bf16& l) {
    h = __float2bfloat16(x); l = __float2bfloat16(x - __bfloat162float(h));
}

#define SST   98304      // stage: Ah 16K | Al 16K | Bh 32K | Bl 32K
#define SMEMT 196608

// ============ mma.sync split-bf16 GEMM: C = act(alpha*A@B^T + bias) ==========
// A rows [*,K] hi/lo bf16, B rows [*,K] hi/lo bf16 (row stride == K).
// CTA tile 128x256, 16 warps (warp tile 32x64), K-chunk 64, cp.async 2-stage.
__global__ void __launch_bounds__(512, 1)
gemm_tc(const bf16* __restrict__ Ah, const bf16* __restrict__ Al,
        const bf16* __restrict__ Bh, const bf16* __restrict__ Bl,
        const float* __restrict__ bias, float* __restrict__ C,
        bf16* __restrict__ Ch, bf16* __restrict__ Cl,
        int K, int ldc, int batch2, int aR1, int aR2, int bR1, int bR2,
        long sC1, long sC2, long sB1, float alpha, int act)
{
    extern __shared__ __align__(1024) char sm[];
    uint32_t sb = smem_u32(sm);
    int tid = threadIdx.x, wid = tid >> 5, lane = tid & 31;
    int z = blockIdx.z, z1 = z / batch2, z2 = z % batch2;
    long aOff = (long)z1*aR1 + (long)z2*aR2 + blockIdx.y*128;
    long bOff = (long)z1*bR1 + (long)z2*bR2 + blockIdx.x*256;
    int warp_m = (wid & 3) * 32, warp_n = (wid >> 2) * 64;

    float acc[2][8][4];
#pragma unroll
    for (int mt = 0; mt < 2; mt++)
#pragma unroll
        for (int nt = 0; nt < 8; nt++)
#pragma unroll
            for (int r = 0; r < 4; r++) acc[mt][nt][r] = 0.f;

    int nkt = K >> 6;
    auto load_stage = [&](int s, int kt) {
        uint32_t base = sb + s * SST;
        long kb = (long)kt * 64;
#pragma unroll
        for (int it = 0; it < 2; it++) {          // A: 128 rows x 8 c16
            int idx = tid + it * 512;
            int r = idx >> 3, c = idx & 7;
            uint32_t off = (uint32_t)(r * 128 + ((c ^ (r & 7)) << 4));
            long gi = (aOff + r) * (long)K + kb + c * 8;
            CPA16(base + off,         Ah + gi);
            CPA16(base + 16384 + off, Al + gi);
        }
#pragma unroll
        for (int it = 0; it < 4; it++) {          // B: 256 rows x 8 c16
            int idx = tid + it * 512;
            int r = idx >> 3, c = idx & 7;
            uint32_t off = (uint32_t)(r * 128 + ((c ^ (r & 7)) << 4));
            long gi = (bOff + r) * (long)K + kb + c * 8;
            CPA16(base + 32768 + off, Bh + gi);
            CPA16(base + 65536 + off, Bl + gi);
        }
    };

    load_stage(0, 0);
    CP_COMMIT();

    for (int kt = 0; kt < nkt; kt++) {
        int s = kt & 1;
        if (kt + 1 < nkt) load_stage(s ^ 1, kt + 1);
        CP_COMMIT();
        CP_WAIT1();
        __syncthreads();

        uint32_t sA_h = sb + s * SST, sA_l = sA_h + 16384;
        uint32_t sB_h = sA_h + 32768, sB_l = sA_h + 65536;
#pragma unroll
        for (int ks = 0; ks < 4; ks++) {
            uint32_t ah[2][4], al[2][4];
#pragma unroll
            for (int mt = 0; mt < 2; mt++) {
                int row = warp_m + mt * 16 + (lane & 15);
                int c16 = ks * 2 + (lane >> 4);
                uint32_t off = (uint32_t)(row * 128 + ((c16 ^ (row & 7)) << 4));
                LDSM4(ah[mt], sA_h + off);
                LDSM4(al[mt], sA_l + off);
            }
#pragma unroll
            for (int p = 0; p < 4; p++) {
                int row = warp_n + p * 16 + ((lane >> 4) << 3) + (lane & 7);
                int c16 = ks * 2 + ((lane >> 3) & 1);
                uint32_t off = (uint32_t)(row * 128 + ((c16 ^ (row & 7)) << 4));
                uint32_t bh[4], bl[4];
                LDSM4(bh, sB_h + off);
                LDSM4(bl, sB_l + off);
                // order: all hh, then lh, then hl -> longer RAW gaps per acc
#pragma unroll
                for (int mt = 0; mt < 2; mt++) {
                    mma16816(acc[mt][2*p],   ah[mt], bh[0], bh[1]);
                    mma16816(acc[mt][2*p+1], ah[mt], bh[2], bh[3]);
                }
#pragma unroll
                for (int mt = 0; mt < 2; mt++) {
                    mma16816(acc[mt][2*p],   al[mt], bh[0], bh[1]);
                    mma16816(acc[mt][2*p+1], al[mt], bh[2], bh[3]);
                }
#pragma unroll
                for (int mt = 0; mt < 2; mt++) {
                    mma16816(acc[mt][2*p],   ah[mt], bl[0], bl[1]);
                    mma16816(acc[mt][2*p+1], ah[mt], bl[2], bl[3]);
                }
            }
        }
        __syncthreads();
    }

    // ---- epilogue ----
    float* Cp = C ? C + z1*sC1 + z2*sC2 : nullptr;
    bf16 *Chp = nullptr, *Clp = nullptr;
    if (Ch) { Chp = Ch + z1*sC1 + z2*sC2; Clp = Cl + z1*sC1 + z2*sC2; }
    const float* bp = bias ? bias + z1*sB1 : nullptr;
    int rowBase = blockIdx.y*128 + warp_m + (lane >> 2);
    int colBase = blockIdx.x*256 + warp_n + (lane & 3) * 2;
#pragma unroll
    for (int mt = 0; mt < 2; mt++) {
#pragma unroll
        for (int nt = 0; nt < 8; nt++) {
#pragma unroll
            for (int hh = 0; hh < 2; hh++) {
                int row = rowBase + mt * 16 + hh * 8;
                int col = colBase + nt * 8;
                float x0 = acc[mt][nt][hh*2]     * alpha;
                float x1 = acc[mt][nt][hh*2 + 1] * alpha;
                if (bp) { x0 += bp[col]; x1 += bp[col + 1]; }
                if (act) { x0 = gelu_exact(x0); x1 = gelu_exact(x1); }
                long o = (long)row * ldc + col;
                if (Cp) *(float2*)(Cp + o) = make_float2(x0, x1);
                if (Chp) {
                    bf16 h0, l0, h1, l1;
                    split_bf(x0, h0, l0); split_bf(x1, h1, l1);
                    *(__nv_bfloat162*)(Chp + o) = __halves2bfloat162(h0, h1);
                    *(__nv_bfloat162*)(Clp + o) = __halves2bfloat162(l0, l1);
                }
            }
        }
    }
}

// ---------------- fp32 -> (hi,lo) bf16 --------------------------------------
__global__ void conv_hl(const float4* __restrict__ x, bf16* __restrict__ h, bf16* __restrict__ l) {
    long i = (long)blockIdx.x*256 + threadIdx.x;
    float4 v = x[i];
    bf16 h0,l0,h1,l1,h2,l2,h3,l3;
    split_bf(v.x,h0,l0); split_bf(v.y,h1,l1); split_bf(v.z,h2,l2); split_bf(v.w,h3,l3);
    __nv_bfloat162* hp = (__nv_bfloat162*)(h + 4*i);
    __nv_bfloat162* lp = (__nv_bfloat162*)(l + 4*i);
    hp[0]=__halves2bfloat162(h0,h1); hp[1]=__halves2bfloat162(h2,h3);
    lp[0]=__halves2bfloat162(l0,l1); lp[1]=__halves2bfloat162(l2,l3);
}

// ------------- transpose+split: in[z][R][Cc] -> out[z][Cc][R] ----------------
__global__ void tconv(const float* __restrict__ in, bf16* __restrict__ oh, bf16* __restrict__ ol, int R, int Cc) {
    __shared__ float t[32][33];
    long base = (long)blockIdx.z * R * Cc;
    int c0 = blockIdx.x*32, r0 = blockIdx.y*32;
#pragma unroll
    for (int i = 0; i < 4; i++)
        t[threadIdx.y + i*8][threadIdx.x] = in[base + (long)(r0 + threadIdx.y + i*8)*Cc + c0 + threadIdx.x];
    __syncthreads();
#pragma unroll
    for (int i = 0; i < 4; i++) {
        int c = c0 + threadIdx.y + i*8, r = r0 + threadIdx.x;
        bf16 h, l; split_bf(t[threadIdx.x][threadIdx.y + i*8], h, l);
        long o = base + (long)c*R + r;
        oh[o] = h; ol[o] = l;
    }
}

// ------------------ causal softmax -> (hi,lo) bf16 ---------------------------
__global__ void softmax_causal(const float* __restrict__ w, bf16* __restrict__ aH, bf16* __restrict__ aL) {
    long row = blockIdx.x;
    int t = (int)(row % Tq), tid = threadIdx.x;
    const float* p = w + row*(long)Tq;
    __shared__ float red[256];
    float vals[4], vmax = -1e30f;
#pragma unroll
    for (int i = 0; i < 4; i++) {
        int j = tid + i*256; float x = p[j]; vals[i] = x;
        if (j <= t && x > vmax) vmax = x;
    }
    red[tid] = vmax; __syncthreads();
    for (int s = 128; s > 0; s >>= 1) { if (tid < s) red[tid] = fmaxf(red[tid], red[tid+s]); __syncthreads(); }
    vmax = red[0]; __syncthreads();
    float sum = 0.f;
#pragma unroll
    for (int i = 0; i < 4; i++) {
        int j = tid + i*256;
        float e = (j <= t) ? expf(vals[i] - vmax) : 0.f;
        vals[i] = e; sum += e;
    }
    red[tid] = sum; __syncthreads();
    for (int s = 128; s > 0; s >>= 1) { if (tid < s) red[tid] += red[tid+s]; __syncthreads(); }
    float inv = 1.f / red[0];
#pragma unroll
    for (int i = 0; i < 4; i++) {
        bf16 h, l; split_bf(vals[i]*inv, h, l);
        long o = row*(long)Tq + tid + i*256;
        aH[o] = h; aL[o] = l;
    }
}

// --- residual+LN: t = x(+y); out = ln_only ? ln(t) : t+ln(t); optional hi/lo -
__global__ void resln(const float* __restrict__ x, const float* __restrict__ y,
                      const float* __restrict__ g, const float* __restrict__ b,
                      float* __restrict__ out, bf16* __restrict__ oh, bf16* __restrict__ ol, int ln_only) {
    long row = blockIdx.x;
    int tid = threadIdx.x;
    const float* px = x + row*(long)Dq;
    const float* py = y ? y + row*(long)Dq : nullptr;
    __shared__ float sh[Dq];
    __shared__ float red[256];
    float ls = 0.f;
    for (int i = tid; i < Dq; i += 256) { float t = px[i] + (py ? py[i] : 0.f); sh[i] = t; ls += t; }
    red[tid] = ls; __syncthreads();
    for (int s = 128; s > 0; s >>= 1) { if (tid < s) red[tid] += red[tid+s]; __syncthreads(); }
    float mean = red[0] * (1.0f/Dq); __syncthreads();
    float lv = 0.f;
    for (int i = tid; i < Dq; i += 256) { float d = sh[i]-mean; lv += d*d; }
    red[tid] = lv; __syncthreads();
    for (int s = 128; s > 0; s >>= 1) { if (tid < s) red[tid] += red[tid+s]; __syncthreads(); }
    float rstd = rsqrtf(red[0]*(1.0f/Dq) + 1e-5f);
    for (int i = tid; i < Dq; i += 256) {
        float t = sh[i];
        float l = (t - mean)*rstd*g[i] + b[i];
        float o = ln_only ? l : t + l;
        long oi = row*(long)Dq + i;
        if (out) out[oi] = o;
        if (oh) { bf16 hh, ll; split_bf(o, hh, ll); oh[oi] = hh; ol[oi] = ll; }
    }
}

// -----------------------------------------------------------------------------
extern "C" void kernel_launch(void* const* d_in, const int* in_sizes, int n_in,
                              void* d_out, int out_size)
{
    const float* src=(const float*)d_in[0]; const float* att=(const float*)d_in[1];
    const float* mWq=(const float*)d_in[2]; const float* mbq=(const float*)d_in[3];
    const float* mWk=(const float*)d_in[4]; const float* mbk=(const float*)d_in[5];
    const float* mWv=(const float*)d_in[6]; const float* dWp=(const float*)d_in[7];
    const float* dbp=(const float*)d_in[8]; const float* dWo=(const float*)d_in[9];
    const float* dbo=(const float*)d_in[10]; const float* fW1=(const float*)d_in[11];
    const float* fb1=(const float*)d_in[12]; const float* fW2=(const float*)d_in[13];
    const float* fb2=(const float*)d_in[14]; const float* g1=(const float*)d_in[15];
    const float* b1=(const float*)d_in[16]; const float* g2=(const float*)d_in[17];
    const float* b2=(const float*)d_in[18];
    float* out = (float*)d_out;

#define SYM(T,p,s) T p; cudaGetSymbolAddress((void**)&p, s)
    SYM(bf16*,srcH,g_srcH); SYM(bf16*,srcL,g_srcL); SYM(bf16*,attH,g_attH); SYM(bf16*,attL,g_attL);
    SYM(bf16*,WqTH,g_WqTH); SYM(bf16*,WqTL,g_WqTL); SYM(bf16*,WkTH,g_WkTH); SYM(bf16*,WkTL,g_WkTL);
    SYM(bf16*,WvTH,g_WvTH); SYM(bf16*,WvTL,g_WvTL);
    SYM(bf16*,qH,g_qH); SYM(bf16*,qL,g_qL); SYM(bf16*,kH,g_kH); SYM(bf16*,kL,g_kL);
    SYM(float*,v,g_v); SYM(bf16*,vTH,g_vTH); SYM(bf16*,vTL,g_vTL);
    SYM(float*,w,g_w); SYM(bf16*,aH,g_aH); SYM(bf16*,aL,g_aL);
    SYM(float*,ocat,g_ocat); SYM(float*,srcA,g_srcA); SYM(bf16*,srcAH,g_srcAH); SYM(bf16*,srcAL,g_srcAL);
    SYM(bf16*,dWpTH,g_dWpTH); SYM(bf16*,dWpTL,g_dWpTL); SYM(bf16*,wpH,g_wpH); SYM(bf16*,wpL,g_wpL);
    SYM(bf16*,o2H,g_o2H); SYM(bf16*,o2L,g_o2L); SYM(bf16*,dWoTH,g_dWoTH); SYM(bf16*,dWoTL,g_dWoTL);
    SYM(float*,o3,g_o3); SYM(float*,trgf,g_trgf); SYM(bf16*,ln2H,g_ln2H); SYM(bf16*,ln2L,g_ln2L);
    SYM(bf16*,fW1TH,g_fW1TH); SYM(bf16*,fW1TL,g_fW1TL); SYM(bf16*,h1H,g_h1H); SYM(bf16*,h1L,g_h1L);
    SYM(bf16*,fW2TH,g_fW2TH); SYM(bf16*,fW2TL,g_fW2TL); SYM(float*,ff,g_ff);

    cudaFuncSetAttribute(gemm_tc, cudaFuncAttributeMaxDynamicSharedMemorySize, SMEMT);
    dim3 tb(32, 8);
    const long TT=(long)Tq*Tq, TD=(long)Tq*Dq, BTD=(long)BT*Dq, BTHS=(long)BT*HSq, BTT=(long)Bq*Tq*Tq;

    // --- launch order arranged so ncu (-s 5 -c 1) captures a GEMM at idx 5 ---
    conv_hl<<<BTD/1024, 256>>>((const float4*)src, srcH, srcL);                 // 0
    tconv<<<dim3(HSq/32, Dq/32, Hq), tb>>>(mWq, WqTH, WqTL, Dq, HSq);           // 1
    tconv<<<dim3(HSq/32, Dq/32, Hq), tb>>>(mWk, WkTH, WkTL, Dq, HSq);           // 2
    tconv<<<dim3(HSq/32, Dq/32, Hq), tb>>>(mWv, WvTH, WvTL, Dq, HSq);           // 3
    gemm_tc<<<dim3(4,64,Hq), 512, SMEMT>>>(srcH, srcL, WqTH, WqTL, mbq, nullptr, qH, qL,
        Dq, HSq, 1, 0,0, HSq,0, BTHS,0, HSq, 1.0f, 0);                          // 4
    gemm_tc<<<dim3(4,64,Hq), 512, SMEMT>>>(srcH, srcL, WkTH, WkTL, mbk, nullptr, kH, kL,
        Dq, HSq, 1, 0,0, HSq,0, BTHS,0, HSq, 1.0f, 0);                          // 5 <- profiled
    gemm_tc<<<dim3(4,64,Hq), 512, SMEMT>>>(srcH, srcL, WvTH, WvTL, nullptr, v, nullptr, nullptr,
        Dq, HSq, 1, 0,0, HSq,0, BTHS,0, 0, 1.0f, 0);                            // 6
    conv_hl<<<BTHS/1024, 256>>>((const float4*)att, attH, attL);
    tconv<<<dim3(Dq/32, HSq/32, Hq), tb>>>(dWp, dWpTH, dWpTL, HSq, Dq);
    tconv<<<dim3(Dq/32, Dq/32, 1), tb>>>(dWo, dWoTH, dWoTL, Dq, Dq);
    tconv<<<dim3(FFq/32, Dq/32, 1), tb>>>(fW1, fW1TH, fW1TL, Dq, FFq);
    tconv<<<dim3(Dq/32, FFq/32, 1), tb>>>(fW2, fW2TH, fW2TL, FFq, Dq);
    tconv<<<dim3(HSq/32, Tq/32, Hq*Bq), tb>>>(v, vTH, vTL, Tq, HSq);

    // scores: per (h,b), [1024,1024] = q @ k^T * 32
    gemm_tc<<<dim3(4,8,Hq*Bq), 512, SMEMT>>>(qH, qL, kH, kL, nullptr, w, nullptr, nullptr,
        HSq, Tq, Bq, BT,Tq, BT,Tq, BTT,TT, 0, 32.0f, 0);
    softmax_causal<<<Hq*Bq*Tq, 256>>>(w, aH, aL);
    // o = a @ vT^T : per (h,b)
    gemm_tc<<<dim3(4,8,Hq*Bq), 512, SMEMT>>>(aH, aL, vTH, vTL, nullptr, ocat, nullptr, nullptr,
        Tq, Dq, Bq, Bq*Tq,Tq, Bq*HSq,HSq, (long)HSq,TD, 0, 1.0f, 0);
    resln<<<BT, 256>>>(src, ocat, g1, b1, srcA, srcAH, srcAL, 0);
    // wp = att @ dWp^T : per head [8192,4096]
    gemm_tc<<<dim3(16,64,Hq), 512, SMEMT>>>(attH, attL, dWpTH, dWpTL, dbp, nullptr, wpH, wpL,
        HSq, Dq, 1, 0,0, Dq,0, BTD,0, Dq, 1.0f, 0);
    // o2 = wp @ srcA^T : per (h,b), [1024,1024], K=4096
    gemm_tc<<<dim3(4,8,Hq*Bq), 512, SMEMT>>>(wpH, wpL, srcAH, srcAL, nullptr, nullptr, o2H, o2L,
        Dq, Dq, Bq, BT,Tq, 0,Tq, (long)Tq,TD, 0, 1.0f, 0);
    // o3 = o2 @ dWo^T
    gemm_tc<<<dim3(16,64,1), 512, SMEMT>>>(o2H, o2L, dWoTH, dWoTL, dbo, o3, nullptr, nullptr,
        Dq, Dq, 1, 0,0, 0,0, 0,0, 0, 1.0f, 0);
    resln<<<BT, 256>>>(srcA, o3, g1, b1, trgf, nullptr, nullptr, 0);
    resln<<<BT, 256>>>(trgf, nullptr, g2, b2, nullptr, ln2H, ln2L, 1);
    // h1 = gelu(ln2 @ fW1^T + fb1)
    gemm_tc<<<dim3(80,64,1), 512, SMEMT>>>(ln2H, ln2L, fW1TH, fW1TL, fb1, nullptr, h1H, h1L,
        Dq, FFq, 1, 0,0, 0,0, 0,0, 0, 1.0f, 1);
    // ff = h1 @ fW2^T + fb2
    gemm_tc<<<dim3(16,64,1), 512, SMEMT>>>(h1H, h1L, fW2TH, fW2TL, fb2, ff, nullptr, nullptr,
        FFq, Dq, 1, 0,0, 0,0, 0,0, 0, 1.0f, 0);
    resln<<<BT, 256>>>(trgf, ff, g2, b2, out, nullptr, nullptr, 1);
}

// round 7
// speedup vs baseline: 1.3424x; 1.3424x over previous
#include <cuda_runtime.h>
#include <cuda_fp16.h>
#include <math.h>
#include <stdint.h>

typedef __half hf;

#define Bq 8
#define Tq 1024
#define Dq 4096
#define Hq 4
#define HSq 1024
#define BT 8192
#define FFq 20480

// ----------------------------- scratch --------------------------------------
__device__ hf g_srcH[(size_t)BT*Dq], g_srcL[(size_t)BT*Dq];
__device__ hf g_attH[(size_t)BT*HSq], g_attL[(size_t)BT*HSq];
__device__ hf g_WqTH[(size_t)Hq*HSq*Dq], g_WqTL[(size_t)Hq*HSq*Dq];
__device__ hf g_WkTH[(size_t)Hq*HSq*Dq], g_WkTL[(size_t)Hq*HSq*Dq];
__device__ hf g_WvTH[(size_t)Hq*HSq*Dq], g_WvTL[(size_t)Hq*HSq*Dq];
__device__ hf g_qH[(size_t)Hq*BT*HSq], g_qL[(size_t)Hq*BT*HSq];
__device__ hf g_kH[(size_t)Hq*BT*HSq], g_kL[(size_t)Hq*BT*HSq];
__device__ float g_v[(size_t)Hq*BT*HSq];
__device__ hf g_vTH[(size_t)Hq*BT*HSq], g_vTL[(size_t)Hq*BT*HSq];
__device__ float g_w[(size_t)Hq*Bq*Tq*Tq];
__device__ hf g_aH[(size_t)Hq*Bq*Tq*Tq], g_aL[(size_t)Hq*Bq*Tq*Tq];
__device__ float g_ocat[(size_t)BT*Dq];
__device__ float g_srcA[(size_t)BT*Dq];
__device__ hf g_srcAH[(size_t)BT*Dq], g_srcAL[(size_t)BT*Dq];
__device__ hf g_dWpTH[(size_t)Hq*Dq*HSq], g_dWpTL[(size_t)Hq*Dq*HSq];
__device__ hf g_wpH[(size_t)Hq*BT*Dq], g_wpL[(size_t)Hq*BT*Dq];
__device__ hf g_o2H[(size_t)BT*Dq], g_o2L[(size_t)BT*Dq];
__device__ hf g_dWoTH[(size_t)Dq*Dq], g_dWoTL[(size_t)Dq*Dq];
__device__ float g_o3[(size_t)BT*Dq];
__device__ float g_trgf[(size_t)BT*Dq];
__device__ hf g_ln2H[(size_t)BT*Dq], g_ln2L[(size_t)BT*Dq];
__device__ hf g_fW1TH[(size_t)FFq*Dq], g_fW1TL[(size_t)FFq*Dq];
__device__ hf g_h1H[(size_t)BT*FFq], g_h1L[(size_t)BT*FFq];
__device__ hf g_fW2TH[(size_t)Dq*FFq], g_fW2TL[(size_t)Dq*FFq];
__device__ float g_ff[(size_t)BT*Dq];

// ----------------------------- helpers --------------------------------------
__device__ __forceinline__ uint32_t smem_u32(const void* p) {
    uint32_t a;
    asm("{ .reg .u64 t; cvta.to.shared.u64 t, %1; cvt.u32.u64 %0, t; }" : "=r"(a) : "l"(p));
    return a;
}
#define CPA16(dst, src) asm volatile("cp.async.cg.shared.global [%0], [%1], 16;" :: "r"((uint32_t)(dst)), "l"(src) : "memory")
#define CP_COMMIT()     asm volatile("cp.async.commit_group;" ::: "memory")
#define CP_WAIT1()      asm volatile("cp.async.wait_group 1;" ::: "memory")
#define LDSM4(r, a) asm volatile("ldmatrix.sync.aligned.m8n8.x4.shared.b16 {%0,%1,%2,%3}, [%4];" \
    : "=r"((r)[0]), "=r"((r)[1]), "=r"((r)[2]), "=r"((r)[3]) : "r"(a))
__device__ __forceinline__ void mma16816(float* d, const uint32_t* a, uint32_t b0, uint32_t b1) {
    asm volatile("mma.sync.aligned.m16n8k16.row.col.f32.f16.f16.f32 "
        "{%0,%1,%2,%3}, {%4,%5,%6,%7}, {%8,%9}, {%0,%1,%2,%3};"
        : "+f"(d[0]), "+f"(d[1]), "+f"(d[2]), "+f"(d[3])
        : "r"(a[0]), "r"(a[1]), "r"(a[2]), "r"(a[3]), "r"(b0), "r"(b1));
}
__device__ __forceinline__ float gelu_exact(float x) { return 0.5f*x*(1.0f+erff(x*0.70710678118654752440f)); }
__device__ __forceinline__ void split_hf(float x, hf& h, hf& l) {
    h = __float2half(x); l = __float2half(x - __half2float(h));
}

#define SST   98304      // stage: Ah 16K | Al 16K | Bh 32K | Bl 32K
#define SMEMT 196608

// ====== mma.sync split-fp16 GEMM: C = act(alpha*A@B^T + bias) ================
// NPROD=3: Ah*Bh + Al*Bh + Ah*Bl (err ~2^-22). NPROD=2: Ah*Bh + Al*Bh (~2^-11/sqrt3).
// causal: 0 none; 1 skip blocks above diagonal (scores); 2 truncate K at diag (AV).
// CTA tile 128x256, 8 warps (warp tile 64x64), K-chunk 64, cp.async 2-stage.
template<int NPROD>
__global__ void __launch_bounds__(256, 1)
gemm_tc(const hf* __restrict__ Ah, const hf* __restrict__ Al,
        const hf* __restrict__ Bh, const hf* __restrict__ Bl,
        const float* __restrict__ bias, float* __restrict__ C,
        hf* __restrict__ Ch, hf* __restrict__ Cl,
        int K, int ldc, int batch2, int aR1, int aR2, int bR1, int bR2,
        long sC1, long sC2, long sB1, float alpha, int act, int causal)
{
    if (causal == 1 && (int)blockIdx.x * 256 > (int)blockIdx.y * 128 + 127) return;
    extern __shared__ __align__(1024) char sm[];
    uint32_t sb = smem_u32(sm);
    int tid = threadIdx.x, wid = tid >> 5, lane = tid & 31;
    int z = blockIdx.z, z1 = z / batch2, z2 = z % batch2;
    long aOff = (long)z1*aR1 + (long)z2*aR2 + blockIdx.y*128;
    long bOff = (long)z1*bR1 + (long)z2*bR2 + blockIdx.x*256;
    int warp_m = (wid & 1) * 64, warp_n = (wid >> 1) * 64;

    float acc[4][8][4];
#pragma unroll
    for (int mt = 0; mt < 4; mt++)
#pragma unroll
        for (int nt = 0; nt < 8; nt++)
#pragma unroll
            for (int r = 0; r < 4; r++) acc[mt][nt][r] = 0.f;

    int nkt = K >> 6;
    if (causal == 2) { int lim = 2 * (int)blockIdx.y + 2; if (lim < nkt) nkt = lim; }

    auto load_stage = [&](int s, int kt) {
        uint32_t base = sb + s * SST;
        long kb = (long)kt * 64;
#pragma unroll
        for (int it = 0; it < 4; it++) {          // A: 128 rows x 8 c16
            int idx = tid + it * 256;
            int r = idx >> 3, c = idx & 7;
            uint32_t off = (uint32_t)(r * 128 + ((c ^ (r & 7)) << 4));
            long gi = (aOff + r) * (long)K + kb + c * 8;
            CPA16(base + off,         Ah + gi);
            CPA16(base + 16384 + off, Al + gi);
        }
#pragma unroll
        for (int it = 0; it < 8; it++) {          // B: 256 rows x 8 c16
            int idx = tid + it * 256;
            int r = idx >> 3, c = idx & 7;
            uint32_t off = (uint32_t)(r * 128 + ((c ^ (r & 7)) << 4));
            long gi = (bOff + r) * (long)K + kb + c * 8;
            CPA16(base + 32768 + off, Bh + gi);
            if (NPROD == 3) CPA16(base + 65536 + off, Bl + gi);
        }
    };

    load_stage(0, 0);
    CP_COMMIT();

    for (int kt = 0; kt < nkt; kt++) {
        int s = kt & 1;
        if (kt + 1 < nkt) load_stage(s ^ 1, kt + 1);
        CP_COMMIT();
        CP_WAIT1();
        __syncthreads();

        uint32_t sA_h = sb + s * SST, sA_l = sA_h + 16384;
        uint32_t sB_h = sA_h + 32768, sB_l = sA_h + 65536;
#pragma unroll
        for (int ks = 0; ks < 4; ks++) {
            uint32_t ah[4][4], al[4][4];
#pragma unroll
            for (int mt = 0; mt < 4; mt++) {
                int row = warp_m + mt * 16 + (lane & 15);
                int c16 = ks * 2 + (lane >> 4);
                uint32_t off = (uint32_t)(row * 128 + ((c16 ^ (row & 7)) << 4));
                LDSM4(ah[mt], sA_h + off);
                LDSM4(al[mt], sA_l + off);
            }
#pragma unroll
            for (int p = 0; p < 4; p++) {
                int row = warp_n + p * 16 + ((lane >> 4) << 3) + (lane & 7);
                int c16 = ks * 2 + ((lane >> 3) & 1);
                uint32_t off = (uint32_t)(row * 128 + ((c16 ^ (row & 7)) << 4));
                uint32_t bh[4];
                LDSM4(bh, sB_h + off);
#pragma unroll
                for (int mt = 0; mt < 4; mt++) {
                    mma16816(acc[mt][2*p],   ah[mt], bh[0], bh[1]);
                    mma16816(acc[mt][2*p],   al[mt], bh[0], bh[1]);
                    mma16816(acc[mt][2*p+1], ah[mt], bh[2], bh[3]);
                    mma16816(acc[mt][2*p+1], al[mt], bh[2], bh[3]);
                }
                if (NPROD == 3) {
                    uint32_t bl[4];
                    LDSM4(bl, sB_l + off);
#pragma unroll
                    for (int mt = 0; mt < 4; mt++) {
                        mma16816(acc[mt][2*p],   ah[mt], bl[0], bl[1]);
                        mma16816(acc[mt][2*p+1], ah[mt], bl[2], bl[3]);
                    }
                }
            }
        }
        __syncthreads();
    }

    // ---- epilogue ----
    float* Cp = C ? C + z1*sC1 + z2*sC2 : nullptr;
    hf *Chp = nullptr, *Clp = nullptr;
    if (Ch) { Chp = Ch + z1*sC1 + z2*sC2; Clp = Cl + z1*sC1 + z2*sC2; }
    const float* bp = bias ? bias + z1*sB1 : nullptr;
    int rowBase = blockIdx.y*128 + warp_m + (lane >> 2);
    int colBase = blockIdx.x*256 + warp_n + (lane & 3) * 2;
#pragma unroll
    for (int mt = 0; mt < 4; mt++) {
#pragma unroll
        for (int nt = 0; nt < 8; nt++) {
#pragma unroll
            for (int hh = 0; hh < 2; hh++) {
                int row = rowBase + mt * 16 + hh * 8;
                int col = colBase + nt * 8;
                float x0 = acc[mt][nt][hh*2]     * alpha;
                float x1 = acc[mt][nt][hh*2 + 1] * alpha;
                if (bp) { x0 += bp[col]; x1 += bp[col + 1]; }
                if (act) { x0 = gelu_exact(x0); x1 = gelu_exact(x1); }
                long o = (long)row * ldc + col;
                if (Cp) *(float2*)(Cp + o) = make_float2(x0, x1);
                if (Chp) {
                    hf h0, l0, h1, l1;
                    split_hf(x0, h0, l0); split_hf(x1, h1, l1);
                    *(__half2*)(Chp + o) = __halves2half2(h0, h1);
                    *(__half2*)(Clp + o) = __halves2half2(l0, l1);
                }
            }
        }
    }
}

// ---------------- fp32 -> (hi,lo) fp16 --------------------------------------
__global__ void conv_hl(const float4* __restrict__ x, hf* __restrict__ h, hf* __restrict__ l) {
    long i = (long)blockIdx.x*256 + threadIdx.x;
    float4 v = x[i];
    hf h0,l0,h1,l1,h2,l2,h3,l3;
    split_hf(v.x,h0,l0); split_hf(v.y,h1,l1); split_hf(v.z,h2,l2); split_hf(v.w,h3,l3);
    __half2* hp = (__half2*)(h + 4*i);
    __half2* lp = (__half2*)(l + 4*i);
    hp[0]=__halves2half2(h0,h1); hp[1]=__halves2half2(h2,h3);
    lp[0]=__halves2half2(l0,l1); lp[1]=__halves2half2(l2,l3);
}

// ------------- transpose+split: in[z][R][Cc] -> out[z][Cc][R] ----------------
__global__ void tconv(const float* __restrict__ in, hf* __restrict__ oh, hf* __restrict__ ol, int R, int Cc) {
    __shared__ float t[32][33];
    long base = (long)blockIdx.z * R * Cc;
    int c0 = blockIdx.x*32, r0 = blockIdx.y*32;
#pragma unroll
    for (int i = 0; i < 4; i++)
        t[threadIdx.y + i*8][threadIdx.x] = in[base + (long)(r0 + threadIdx.y + i*8)*Cc + c0 + threadIdx.x];
    __syncthreads();
#pragma unroll
    for (int i = 0; i < 4; i++) {
        int c = c0 + threadIdx.y + i*8, r = r0 + threadIdx.x;
        hf h, l; split_hf(t[threadIdx.x][threadIdx.y + i*8], h, l);
        long o = base + (long)c*R + r;
        oh[o] = h; ol[o] = l;
    }
}

// ------------------ causal softmax -> (hi,lo) fp16 ---------------------------
__global__ void softmax_causal(const float* __restrict__ w, hf* __restrict__ aH, hf* __restrict__ aL) {
    long row = blockIdx.x;
    int t = (int)(row % Tq), tid = threadIdx.x;
    const float* p = w + row*(long)Tq;
    __shared__ float red[256];
    float vals[4], vmax = -1e30f;
#pragma unroll
    for (int i = 0; i < 4; i++) {
        int j = tid + i*256; float x = p[j]; vals[i] = x;
        if (j <= t && x > vmax) vmax = x;
    }
    red[tid] = vmax; __syncthreads();
    for (int s = 128; s > 0; s >>= 1) { if (tid < s) red[tid] = fmaxf(red[tid], red[tid+s]); __syncthreads(); }
    vmax = red[0]; __syncthreads();
    float sum = 0.f;
#pragma unroll
    for (int i = 0; i < 4; i++) {
        int j = tid + i*256;
        float e = (j <= t) ? expf(vals[i] - vmax) : 0.f;
        vals[i] = e; sum += e;
    }
    red[tid] = sum; __syncthreads();
    for (int s = 128; s > 0; s >>= 1) { if (tid < s) red[tid] += red[tid+s]; __syncthreads(); }
    float inv = 1.f / red[0];
#pragma unroll
    for (int i = 0; i < 4; i++) {
        hf h, l; split_hf(vals[i]*inv, h, l);
        long o = row*(long)Tq + tid + i*256;
        aH[o] = h; aL[o] = l;
    }
}

// --- residual+LN: t = x(+y); out = ln_only ? ln(t) : t+ln(t); optional hi/lo -
__global__ void resln(const float* __restrict__ x, const float* __restrict__ y,
                      const float* __restrict__ g, const float* __restrict__ b,
                      float* __restrict__ out, hf* __restrict__ oh, hf* __restrict__ ol, int ln_only) {
    long row = blockIdx.x;
    int tid = threadIdx.x;
    const float* px = x + row*(long)Dq;
    const float* py = y ? y + row*(long)Dq : nullptr;
    __shared__ float sh[Dq];
    __shared__ float red[256];
    float ls = 0.f;
    for (int i = tid; i < Dq; i += 256) { float t = px[i] + (py ? py[i] : 0.f); sh[i] = t; ls += t; }
    red[tid] = ls; __syncthreads();
    for (int s = 128; s > 0; s >>= 1) { if (tid < s) red[tid] += red[tid+s]; __syncthreads(); }
    float mean = red[0] * (1.0f/Dq); __syncthreads();
    float lv = 0.f;
    for (int i = tid; i < Dq; i += 256) { float d = sh[i]-mean; lv += d*d; }
    red[tid] = lv; __syncthreads();
    for (int s = 128; s > 0; s >>= 1) { if (tid < s) red[tid] += red[tid+s]; __syncthreads(); }
    float rstd = rsqrtf(red[0]*(1.0f/Dq) + 1e-5f);
    for (int i = tid; i < Dq; i += 256) {
        float t = sh[i];
        float l = (t - mean)*rstd*g[i] + b[i];
        float o = ln_only ? l : t + l;
        long oi = row*(long)Dq + i;
        if (out) out[oi] = o;
        if (oh) { hf hh, ll; split_hf(o, hh, ll); oh[oi] = hh; ol[oi] = ll; }
    }
}

// -----------------------------------------------------------------------------
extern "C" void kernel_launch(void* const* d_in, const int* in_sizes, int n_in,
                              void* d_out, int out_size)
{
    const float* src=(const float*)d_in[0]; const float* att=(const float*)d_in[1];
    const float* mWq=(const float*)d_in[2]; const float* mbq=(const float*)d_in[3];
    const float* mWk=(const float*)d_in[4]; const float* mbk=(const float*)d_in[5];
    const float* mWv=(const float*)d_in[6]; const float* dWp=(const float*)d_in[7];
    const float* dbp=(const float*)d_in[8]; const float* dWo=(const float*)d_in[9];
    const float* dbo=(const float*)d_in[10]; const float* fW1=(const float*)d_in[11];
    const float* fb1=(const float*)d_in[12]; const float* fW2=(const float*)d_in[13];
    const float* fb2=(const float*)d_in[14]; const float* g1=(const float*)d_in[15];
    const float* b1=(const float*)d_in[16]; const float* g2=(const float*)d_in[17];
    const float* b2=(const float*)d_in[18];
    float* out = (float*)d_out;

#define SYM(T,p,s) T p; cudaGetSymbolAddress((void**)&p, s)
    SYM(hf*,srcH,g_srcH); SYM(hf*,srcL,g_srcL); SYM(hf*,attH,g_attH); SYM(hf*,attL,g_attL);
    SYM(hf*,WqTH,g_WqTH); SYM(hf*,WqTL,g_WqTL); SYM(hf*,WkTH,g_WkTH); SYM(hf*,WkTL,g_WkTL);
    SYM(hf*,WvTH,g_WvTH); SYM(hf*,WvTL,g_WvTL);
    SYM(hf*,qH,g_qH); SYM(hf*,qL,g_qL); SYM(hf*,kH,g_kH); SYM(hf*,kL,g_kL);
    SYM(float*,v,g_v); SYM(hf*,vTH,g_vTH); SYM(hf*,vTL,g_vTL);
    SYM(float*,w,g_w); SYM(hf*,aH,g_aH); SYM(hf*,aL,g_aL);
    SYM(float*,ocat,g_ocat); SYM(float*,srcA,g_srcA); SYM(hf*,srcAH,g_srcAH); SYM(hf*,srcAL,g_srcAL);
    SYM(hf*,dWpTH,g_dWpTH); SYM(hf*,dWpTL,g_dWpTL); SYM(hf*,wpH,g_wpH); SYM(hf*,wpL,g_wpL);
    SYM(hf*,o2H,g_o2H); SYM(hf*,o2L,g_o2L); SYM(hf*,dWoTH,g_dWoTH); SYM(hf*,dWoTL,g_dWoTL);
    SYM(float*,o3,g_o3); SYM(float*,trgf,g_trgf); SYM(hf*,ln2H,g_ln2H); SYM(hf*,ln2L,g_ln2L);
    SYM(hf*,fW1TH,g_fW1TH); SYM(hf*,fW1TL,g_fW1TL); SYM(hf*,h1H,g_h1H); SYM(hf*,h1L,g_h1L);
    SYM(hf*,fW2TH,g_fW2TH); SYM(hf*,fW2TL,g_fW2TL); SYM(float*,ff,g_ff);

    cudaFuncSetAttribute(gemm_tc<2>, cudaFuncAttributeMaxDynamicSharedMemorySize, SMEMT);
    cudaFuncSetAttribute(gemm_tc<3>, cudaFuncAttributeMaxDynamicSharedMemorySize, SMEMT);
    dim3 tb(32, 8);
    const long TT=(long)Tq*Tq, TD=(long)Tq*Dq, BTD=(long)BT*Dq, BTHS=(long)BT*HSq, BTT=(long)Bq*Tq*Tq;

    // operand prep
    conv_hl<<<BTD/1024, 256>>>((const float4*)src, srcH, srcL);
    conv_hl<<<BTHS/1024, 256>>>((const float4*)att, attH, attL);
    tconv<<<dim3(HSq/32, Dq/32, Hq), tb>>>(mWq, WqTH, WqTL, Dq, HSq);
    tconv<<<dim3(HSq/32, Dq/32, Hq), tb>>>(mWk, WkTH, WkTL, Dq, HSq);
    tconv<<<dim3(HSq/32, Dq/32, Hq), tb>>>(mWv, WvTH, WvTL, Dq, HSq);
    tconv<<<dim3(Dq/32, HSq/32, Hq), tb>>>(dWp, dWpTH, dWpTL, HSq, Dq);
    tconv<<<dim3(Dq/32, Dq/32, 1), tb>>>(dWo, dWoTH, dWoTL, Dq, Dq);
    tconv<<<dim3(FFq/32, Dq/32, 1), tb>>>(fW1, fW1TH, fW1TL, Dq, FFq);
    tconv<<<dim3(Dq/32, FFq/32, 1), tb>>>(fW2, fW2TH, fW2TL, FFq, Dq);

    // q,k (3-product: feeds softmax amplification), v (2-product)
    gemm_tc<3><<<dim3(4,64,Hq), 256, SMEMT>>>(srcH, srcL, WqTH, WqTL, mbq, nullptr, qH, qL,
        Dq, HSq, 1, 0,0, HSq,0, BTHS,0, HSq, 1.0f, 0, 0);
    gemm_tc<3><<<dim3(4,64,Hq), 256, SMEMT>>>(srcH, srcL, WkTH, WkTL, mbk, nullptr, kH, kL,
        Dq, HSq, 1, 0,0, HSq,0, BTHS,0, HSq, 1.0f, 0, 0);
    gemm_tc<2><<<dim3(4,64,Hq), 256, SMEMT>>>(srcH, srcL, WvTH, WvTL, nullptr, v, nullptr, nullptr,
        Dq, HSq, 1, 0,0, HSq,0, BTHS,0, 0, 1.0f, 0, 0);
    tconv<<<dim3(HSq/32, Tq/32, Hq*Bq), tb>>>(v, vTH, vTL, Tq, HSq);
    // scores: per (h,b), [1024,1024] = q @ k^T * 32 ; 3-product, causal block-skip
    gemm_tc<3><<<dim3(4,8,Hq*Bq), 256, SMEMT>>>(qH, qL, kH, kL, nullptr, w, nullptr, nullptr,
        HSq, Tq, Bq, BT,Tq, BT,Tq, BTT,TT, 0, 32.0f, 0, 1);
    softmax_causal<<<Hq*Bq*Tq, 256>>>(w, aH, aL);
    // o = a @ vT^T : per (h,b); 2-product, K truncated at diagonal
    gemm_tc<2><<<dim3(4,8,Hq*Bq), 256, SMEMT>>>(aH, aL, vTH, vTL, nullptr, ocat, nullptr, nullptr,
        Tq, Dq, Bq, Bq*Tq,Tq, Bq*HSq,HSq, (long)HSq,TD, 0, 1.0f, 0, 2);
    resln<<<BT, 256>>>(src, ocat, g1, b1, srcA, srcAH, srcAL, 0);
    // wp = att @ dWp^T : per head [8192,4096]
    gemm_tc<2><<<dim3(16,64,Hq), 256, SMEMT>>>(attH, attL, dWpTH, dWpTL, dbp, nullptr, wpH, wpL,
        HSq, Dq, 1, 0,0, Dq,0, BTD,0, Dq, 1.0f, 0, 0);
    // o2 = wp @ srcA^T : per (h,b), [1024,1024], K=4096
    gemm_tc<2><<<dim3(4,8,Hq*Bq), 256, SMEMT>>>(wpH, wpL, srcAH, srcAL, nullptr, nullptr, o2H, o2L,
        Dq, Dq, Bq, BT,Tq, 0,Tq, (long)Tq,TD, 0, 1.0f, 0, 0);
    // o3 = o2 @ dWo^T
    gemm_tc<2><<<dim3(16,64,1), 256, SMEMT>>>(o2H, o2L, dWoTH, dWoTL, dbo, o3, nullptr, nullptr,
        Dq, Dq, 1, 0,0, 0,0, 0,0, 0, 1.0f, 0, 0);
    resln<<<BT, 256>>>(srcA, o3, g1, b1, trgf, nullptr, nullptr, 0);
    resln<<<BT, 256>>>(trgf, nullptr, g2, b2, nullptr, ln2H, ln2L, 1);
    // h1 = gelu(ln2 @ fW1^T + fb1)
    gemm_tc<2><<<dim3(80,64,1), 256, SMEMT>>>(ln2H, ln2L, fW1TH, fW1TL, fb1, nullptr, h1H, h1L,
        Dq, FFq, 1, 0,0, 0,0, 0,0, 0, 1.0f, 1, 0);
    // ff = h1 @ fW2^T + fb2
    gemm_tc<2><<<dim3(16,64,1), 256, SMEMT>>>(h1H, h1L, fW2TH, fW2TL, fb2, ff, nullptr, nullptr,
        FFq, Dq, 1, 0,0, 0,0, 0,0, 0, 1.0f, 0, 0);
    resln<<<BT, 256>>>(trgf, ff, g2, b2, out, nullptr, nullptr, 1);
}

// round 8
// speedup vs baseline: 1.7670x; 1.3162x over previous
#include <cuda_runtime.h>
#include <cuda_fp16.h>
#include <math.h>
#include <stdint.h>

typedef __half hf;

#define Bq 8
#define Tq 1024
#define Dq 4096
#define Hq 4
#define HSq 1024
#define BT 8192
#define FFq 20480

// ----------------------------- scratch --------------------------------------
__device__ hf g_srcH[(size_t)BT*Dq], g_srcL[(size_t)BT*Dq];
__device__ hf g_attH[(size_t)BT*HSq], g_attL[(size_t)BT*HSq];
__device__ hf g_WqTH[(size_t)Hq*HSq*Dq], g_WqTL[(size_t)Hq*HSq*Dq];
__device__ hf g_WkTH[(size_t)Hq*HSq*Dq], g_WkTL[(size_t)Hq*HSq*Dq];
__device__ hf g_WvTH[(size_t)Hq*HSq*Dq], g_WvTL[(size_t)Hq*HSq*Dq];
__device__ hf g_qH[(size_t)Hq*BT*HSq], g_qL[(size_t)Hq*BT*HSq];
__device__ hf g_kH[(size_t)Hq*BT*HSq], g_kL[(size_t)Hq*BT*HSq];
__device__ float g_v[(size_t)Hq*BT*HSq];
__device__ hf g_vTH[(size_t)Hq*BT*HSq], g_vTL[(size_t)Hq*BT*HSq];
__device__ float g_w[(size_t)Hq*Bq*Tq*Tq];
__device__ hf g_aH[(size_t)Hq*Bq*Tq*Tq], g_aL[(size_t)Hq*Bq*Tq*Tq];
__device__ float g_ocat[(size_t)BT*Dq];
__device__ float g_srcA[(size_t)BT*Dq];
__device__ hf g_srcAH[(size_t)BT*Dq], g_srcAL[(size_t)BT*Dq];
__device__ hf g_dWpTH[(size_t)Hq*Dq*HSq], g_dWpTL[(size_t)Hq*Dq*HSq];
__device__ hf g_wpH[(size_t)Hq*BT*Dq], g_wpL[(size_t)Hq*BT*Dq];
__device__ hf g_o2H[(size_t)BT*Dq], g_o2L[(size_t)BT*Dq];
__device__ hf g_dWoTH[(size_t)Dq*Dq], g_dWoTL[(size_t)Dq*Dq];
__device__ float g_o3[(size_t)BT*Dq];
__device__ float g_trgf[(size_t)BT*Dq];
__device__ hf g_ln2H[(size_t)BT*Dq];
__device__ hf g_fW1TH[(size_t)FFq*Dq];
__device__ hf g_h1H[(size_t)BT*FFq];
__device__ hf g_fW2TH[(size_t)Dq*FFq];
__device__ float g_ff[(size_t)BT*Dq];

// ----------------------------- helpers --------------------------------------
__device__ __forceinline__ uint32_t smem_u32(const void* p) {
    uint32_t a;
    asm("{ .reg .u64 t; cvta.to.shared.u64 t, %1; cvt.u32.u64 %0, t; }" : "=r"(a) : "l"(p));
    return a;
}
#define CPA16(dst, src) asm volatile("cp.async.cg.shared.global [%0], [%1], 16;" :: "r"((uint32_t)(dst)), "l"(src) : "memory")
#define CP_COMMIT()     asm volatile("cp.async.commit_group;" ::: "memory")
#define CP_WAIT1()      asm volatile("cp.async.wait_group 1;" ::: "memory")
#define LDSM4(r, a) asm volatile("ldmatrix.sync.aligned.m8n8.x4.shared.b16 {%0,%1,%2,%3}, [%4];" \
    : "=r"((r)[0]), "=r"((r)[1]), "=r"((r)[2]), "=r"((r)[3]) : "r"(a))
__device__ __forceinline__ void mma16816(float* d, const uint32_t* a, uint32_t b0, uint32_t b1) {
    asm volatile("mma.sync.aligned.m16n8k16.row.col.f32.f16.f16.f32 "
        "{%0,%1,%2,%3}, {%4,%5,%6,%7}, {%8,%9}, {%0,%1,%2,%3};"
        : "+f"(d[0]), "+f"(d[1]), "+f"(d[2]), "+f"(d[3])
        : "r"(a[0]), "r"(a[1]), "r"(a[2]), "r"(a[3]), "r"(b0), "r"(b1));
}
__device__ __forceinline__ float gelu_exact(float x) { return 0.5f*x*(1.0f+erff(x*0.70710678118654752440f)); }
__device__ __forceinline__ void split_hf(float x, hf& h, hf& l) {
    h = __float2half(x); l = __float2half(x - __half2float(h));
}

#define SST   98304      // stage: Ah 16K | Al 16K | Bh 32K | Bl 32K
#define SMEMT 196608

// ====== mma.sync split-fp16 GEMM: C = act(alpha*A@B^T + bias) ================
// NPROD=3: Ah*Bh+Al*Bh+Ah*Bl (~2^-22). NPROD=2: Ah*Bh+Al*Bh (~2.8e-4).
// NPROD=1: Ah*Bh (~4.9e-4) -- for error-diluted paths (FF).
// causal: 0 none; 1 skip blocks above diagonal; 2 truncate K at diagonal.
// CTA tile 128x256, 8 warps (warp tile 64x64), K-chunk 64, cp.async 2-stage.
template<int NPROD>
__global__ void __launch_bounds__(256, 1)
gemm_tc(const hf* __restrict__ Ah, const hf* __restrict__ Al,
        const hf* __restrict__ Bh, const hf* __restrict__ Bl,
        const float* __restrict__ bias, float* __restrict__ C,
        hf* __restrict__ Ch, hf* __restrict__ Cl,
        int K, int ldc, int batch2, int aR1, int aR2, int bR1, int bR2,
        long sC1, long sC2, long sB1, float alpha, int act, int causal)
{
    if (causal == 1 && (int)blockIdx.x * 256 > (int)blockIdx.y * 128 + 127) return;
    extern __shared__ __align__(1024) char sm[];
    uint32_t sb = smem_u32(sm);
    int tid = threadIdx.x, wid = tid >> 5, lane = tid & 31;
    int z = blockIdx.z, z1 = z / batch2, z2 = z % batch2;
    long aOff = (long)z1*aR1 + (long)z2*aR2 + blockIdx.y*128;
    long bOff = (long)z1*bR1 + (long)z2*bR2 + blockIdx.x*256;
    int warp_m = (wid & 1) * 64, warp_n = (wid >> 1) * 64;

    float acc[4][8][4];
#pragma unroll
    for (int mt = 0; mt < 4; mt++)
#pragma unroll
        for (int nt = 0; nt < 8; nt++)
#pragma unroll
            for (int r = 0; r < 4; r++) acc[mt][nt][r] = 0.f;

    int nkt = K >> 6;
    if (causal == 2) { int lim = 2 * (int)blockIdx.y + 2; if (lim < nkt) nkt = lim; }

    auto load_stage = [&](int s, int kt) {
        uint32_t base = sb + s * SST;
        long kb = (long)kt * 64;
#pragma unroll
        for (int it = 0; it < 4; it++) {          // A: 128 rows x 8 c16
            int idx = tid + it * 256;
            int r = idx >> 3, c = idx & 7;
            uint32_t off = (uint32_t)(r * 128 + ((c ^ (r & 7)) << 4));
            long gi = (aOff + r) * (long)K + kb + c * 8;
            CPA16(base + off, Ah + gi);
            if (NPROD >= 2) CPA16(base + 16384 + off, Al + gi);
        }
#pragma unroll
        for (int it = 0; it < 8; it++) {          // B: 256 rows x 8 c16
            int idx = tid + it * 256;
            int r = idx >> 3, c = idx & 7;
            uint32_t off = (uint32_t)(r * 128 + ((c ^ (r & 7)) << 4));
            long gi = (bOff + r) * (long)K + kb + c * 8;
            CPA16(base + 32768 + off, Bh + gi);
            if (NPROD == 3) CPA16(base + 65536 + off, Bl + gi);
        }
    };

    load_stage(0, 0);
    CP_COMMIT();

    for (int kt = 0; kt < nkt; kt++) {
        int s = kt & 1;
        if (kt + 1 < nkt) load_stage(s ^ 1, kt + 1);
        CP_COMMIT();
        CP_WAIT1();
        __syncthreads();

        uint32_t sA_h = sb + s * SST, sA_l = sA_h + 16384;
        uint32_t sB_h = sA_h + 32768, sB_l = sA_h + 65536;
#pragma unroll
        for (int ks = 0; ks < 4; ks++) {
            uint32_t ah[4][4], al[4][4];
#pragma unroll
            for (int mt = 0; mt < 4; mt++) {
                int row = warp_m + mt * 16 + (lane & 15);
                int c16 = ks * 2 + (lane >> 4);
                uint32_t off = (uint32_t)(row * 128 + ((c16 ^ (row & 7)) << 4));
                LDSM4(ah[mt], sA_h + off);
                if (NPROD >= 2) LDSM4(al[mt], sA_l + off);
            }
#pragma unroll
            for (int p = 0; p < 4; p++) {
                int row = warp_n + p * 16 + ((lane >> 4) << 3) + (lane & 7);
                int c16 = ks * 2 + ((lane >> 3) & 1);
                uint32_t off = (uint32_t)(row * 128 + ((c16 ^ (row & 7)) << 4));
                uint32_t bh[4];
                LDSM4(bh, sB_h + off);
#pragma unroll
                for (int mt = 0; mt < 4; mt++) {
                    mma16816(acc[mt][2*p],   ah[mt], bh[0], bh[1]);
                    mma16816(acc[mt][2*p+1], ah[mt], bh[2], bh[3]);
                }
                if (NPROD >= 2) {
#pragma unroll
                    for (int mt = 0; mt < 4; mt++) {
                        mma16816(acc[mt][2*p],   al[mt], bh[0], bh[1]);
                        mma16816(acc[mt][2*p+1], al[mt], bh[2], bh[3]);
                    }
                }
                if (NPROD == 3) {
                    uint32_t bl[4];
                    LDSM4(bl, sB_l + off);
#pragma unroll
                    for (int mt = 0; mt < 4; mt++) {
                        mma16816(acc[mt][2*p],   ah[mt], bl[0], bl[1]);
                        mma16816(acc[mt][2*p+1], ah[mt], bl[2], bl[3]);
                    }
                }
            }
        }
        __syncthreads();
    }

    // ---- epilogue ----
    float* Cp = C ? C + z1*sC1 + z2*sC2 : nullptr;
    hf *Chp = Ch ? Ch + z1*sC1 + z2*sC2 : nullptr;
    hf *Clp = Cl ? Cl + z1*sC1 + z2*sC2 : nullptr;
    const float* bp = bias ? bias + z1*sB1 : nullptr;
    int rowBase = blockIdx.y*128 + warp_m + (lane >> 2);
    int colBase = blockIdx.x*256 + warp_n + (lane & 3) * 2;
#pragma unroll
    for (int mt = 0; mt < 4; mt++) {
#pragma unroll
        for (int nt = 0; nt < 8; nt++) {
#pragma unroll
            for (int hh = 0; hh < 2; hh++) {
                int row = rowBase + mt * 16 + hh * 8;
                int col = colBase + nt * 8;
                float x0 = acc[mt][nt][hh*2]     * alpha;
                float x1 = acc[mt][nt][hh*2 + 1] * alpha;
                if (bp) { x0 += bp[col]; x1 += bp[col + 1]; }
                if (act) { x0 = gelu_exact(x0); x1 = gelu_exact(x1); }
                long o = (long)row * ldc + col;
                if (Cp) *(float2*)(Cp + o) = make_float2(x0, x1);
                if (Chp) {
                    hf h0, l0, h1, l1;
                    split_hf(x0, h0, l0); split_hf(x1, h1, l1);
                    *(__half2*)(Chp + o) = __halves2half2(h0, h1);
                    if (Clp) *(__half2*)(Clp + o) = __halves2half2(l0, l1);
                }
            }
        }
    }
}

// ---------------- fp32 -> (hi,lo) fp16 --------------------------------------
__global__ void conv_hl(const float4* __restrict__ x, hf* __restrict__ h, hf* __restrict__ l) {
    long i = (long)blockIdx.x*256 + threadIdx.x;
    float4 v = x[i];
    hf h0,l0,h1,l1,h2,l2,h3,l3;
    split_hf(v.x,h0,l0); split_hf(v.y,h1,l1); split_hf(v.z,h2,l2); split_hf(v.w,h3,l3);
    __half2* hp = (__half2*)(h + 4*i);
    __half2* lp = (__half2*)(l + 4*i);
    hp[0]=__halves2half2(h0,h1); hp[1]=__halves2half2(h2,h3);
    lp[0]=__halves2half2(l0,l1); lp[1]=__halves2half2(l2,l3);
}

// ------------- transpose+split: in[z][R][Cc] -> out[z][Cc][R] ----------------
__global__ void tconv(const float* __restrict__ in, hf* __restrict__ oh, hf* __restrict__ ol, int R, int Cc) {
    __shared__ float t[32][33];
    long base = (long)blockIdx.z * R * Cc;
    int c0 = blockIdx.x*32, r0 = blockIdx.y*32;
#pragma unroll
    for (int i = 0; i < 4; i++)
        t[threadIdx.y + i*8][threadIdx.x] = in[base + (long)(r0 + threadIdx.y + i*8)*Cc + c0 + threadIdx.x];
    __syncthreads();
#pragma unroll
    for (int i = 0; i < 4; i++) {
        int c = c0 + threadIdx.y + i*8, r = r0 + threadIdx.x;
        hf h, l; split_hf(t[threadIdx.x][threadIdx.y + i*8], h, l);
        long o = base + (long)c*R + r;
        oh[o] = h;
        if (ol) ol[o] = l;
    }
}

// ------------------ causal softmax -> (hi,lo) fp16 ---------------------------
__global__ void softmax_causal(const float* __restrict__ w, hf* __restrict__ aH, hf* __restrict__ aL) {
    long row = blockIdx.x;
    int t = (int)(row % Tq), tid = threadIdx.x;
    const float* p = w + row*(long)Tq;
    __shared__ float red[256];
    float vals[4], vmax = -1e30f;
#pragma unroll
    for (int i = 0; i < 4; i++) {
        int j = tid + i*256; float x = p[j]; vals[i] = x;
        if (j <= t && x > vmax) vmax = x;
    }
    red[tid] = vmax; __syncthreads();
    for (int s = 128; s > 0; s >>= 1) { if (tid < s) red[tid] = fmaxf(red[tid], red[tid+s]); __syncthreads(); }
    vmax = red[0]; __syncthreads();
    float sum = 0.f;
#pragma unroll
    for (int i = 0; i < 4; i++) {
        int j = tid + i*256;
        float e = (j <= t) ? expf(vals[i] - vmax) : 0.f;
        vals[i] = e; sum += e;
    }
    red[tid] = sum; __syncthreads();
    for (int s = 128; s > 0; s >>= 1) { if (tid < s) red[tid] += red[tid+s]; __syncthreads(); }
    float inv = 1.f / red[0];
#pragma unroll
    for (int i = 0; i < 4; i++) {
        hf h, l; split_hf(vals[i]*inv, h, l);
        long o = row*(long)Tq + tid + i*256;
        aH[o] = h; aL[o] = l;
    }
}

// --- residual+LN: t = x(+y); out = ln_only ? ln(t) : t+ln(t); optional hi/lo -
__global__ void resln(const float* __restrict__ x, const float* __restrict__ y,
                      const float* __restrict__ g, const float* __restrict__ b,
                      float* __restrict__ out, hf* __restrict__ oh, hf* __restrict__ ol, int ln_only) {
    long row = blockIdx.x;
    int tid = threadIdx.x;
    const float* px = x + row*(long)Dq;
    const float* py = y ? y + row*(long)Dq : nullptr;
    __shared__ float sh[Dq];
    __shared__ float red[256];
    float ls = 0.f;
    for (int i = tid; i < Dq; i += 256) { float t = px[i] + (py ? py[i] : 0.f); sh[i] = t; ls += t; }
    red[tid] = ls; __syncthreads();
    for (int s = 128; s > 0; s >>= 1) { if (tid < s) red[tid] += red[tid+s]; __syncthreads(); }
    float mean = red[0] * (1.0f/Dq); __syncthreads();
    float lv = 0.f;
    for (int i = tid; i < Dq; i += 256) { float d = sh[i]-mean; lv += d*d; }
    red[tid] = lv; __syncthreads();
    for (int s = 128; s > 0; s >>= 1) { if (tid < s) red[tid] += red[tid+s]; __syncthreads(); }
    float rstd = rsqrtf(red[0]*(1.0f/Dq) + 1e-5f);
    for (int i = tid; i < Dq; i += 256) {
        float t = sh[i];
        float l = (t - mean)*rstd*g[i] + b[i];
        float o = ln_only ? l : t + l;
        long oi = row*(long)Dq + i;
        if (out) out[oi] = o;
        if (oh) {
            hf hh, ll; split_hf(o, hh, ll);
            oh[oi] = hh;
            if (ol) ol[oi] = ll;
        }
    }
}

// -----------------------------------------------------------------------------
extern "C" void kernel_launch(void* const* d_in, const int* in_sizes, int n_in,
                              void* d_out, int out_size)
{
    const float* src=(const float*)d_in[0]; const float* att=(const float*)d_in[1];
    const float* mWq=(const float*)d_in[2]; const float* mbq=(const float*)d_in[3];
    const float* mWk=(const float*)d_in[4]; const float* mbk=(const float*)d_in[5];
    const float* mWv=(const float*)d_in[6]; const float* dWp=(const float*)d_in[7];
    const float* dbp=(const float*)d_in[8]; const float* dWo=(const float*)d_in[9];
    const float* dbo=(const float*)d_in[10]; const float* fW1=(const float*)d_in[11];
    const float* fb1=(const float*)d_in[12]; const float* fW2=(const float*)d_in[13];
    const float* fb2=(const float*)d_in[14]; const float* g1=(const float*)d_in[15];
    const float* b1=(const float*)d_in[16]; const float* g2=(const float*)d_in[17];
    const float* b2=(const float*)d_in[18];
    float* out = (float*)d_out;

#define SYM(T,p,s) T p; cudaGetSymbolAddress((void**)&p, s)
    SYM(hf*,srcH,g_srcH); SYM(hf*,srcL,g_srcL); SYM(hf*,attH,g_attH); SYM(hf*,attL,g_attL);
    SYM(hf*,WqTH,g_WqTH); SYM(hf*,WqTL,g_WqTL); SYM(hf*,WkTH,g_WkTH); SYM(hf*,WkTL,g_WkTL);
    SYM(hf*,WvTH,g_WvTH); SYM(hf*,WvTL,g_WvTL);
    SYM(hf*,qH,g_qH); SYM(hf*,qL,g_qL); SYM(hf*,kH,g_kH); SYM(hf*,kL,g_kL);
    SYM(float*,v,g_v); SYM(hf*,vTH,g_vTH); SYM(hf*,vTL,g_vTL);
    SYM(float*,w,g_w); SYM(hf*,aH,g_aH); SYM(hf*,aL,g_aL);
    SYM(float*,ocat,g_ocat); SYM(float*,srcA,g_srcA); SYM(hf*,srcAH,g_srcAH); SYM(hf*,srcAL,g_srcAL);
    SYM(hf*,dWpTH,g_dWpTH); SYM(hf*,dWpTL,g_dWpTL); SYM(hf*,wpH,g_wpH); SYM(hf*,wpL,g_wpL);
    SYM(hf*,o2H,g_o2H); SYM(hf*,o2L,g_o2L); SYM(hf*,dWoTH,g_dWoTH); SYM(hf*,dWoTL,g_dWoTL);
    SYM(float*,o3,g_o3); SYM(float*,trgf,g_trgf); SYM(hf*,ln2H,g_ln2H);
    SYM(hf*,fW1TH,g_fW1TH); SYM(hf*,h1H,g_h1H);
    SYM(hf*,fW2TH,g_fW2TH); SYM(float*,ff,g_ff);

    cudaFuncSetAttribute(gemm_tc<1>, cudaFuncAttributeMaxDynamicSharedMemorySize, SMEMT);
    cudaFuncSetAttribute(gemm_tc<2>, cudaFuncAttributeMaxDynamicSharedMemorySize, SMEMT);
    cudaFuncSetAttribute(gemm_tc<3>, cudaFuncAttributeMaxDynamicSharedMemorySize, SMEMT);
    dim3 tb(32, 8);
    const long TT=(long)Tq*Tq, TD=(long)Tq*Dq, BTD=(long)BT*Dq, BTHS=(long)BT*HSq, BTT=(long)Bq*Tq*Tq;

    // operand prep
    conv_hl<<<BTD/1024, 256>>>((const float4*)src, srcH, srcL);
    conv_hl<<<BTHS/1024, 256>>>((const float4*)att, attH, attL);
    tconv<<<dim3(HSq/32, Dq/32, Hq), tb>>>(mWq, WqTH, WqTL, Dq, HSq);
    tconv<<<dim3(HSq/32, Dq/32, Hq), tb>>>(mWk, WkTH, WkTL, Dq, HSq);
    tconv<<<dim3(HSq/32, Dq/32, Hq), tb>>>(mWv, WvTH, WvTL, Dq, HSq);
    tconv<<<dim3(Dq/32, HSq/32, Hq), tb>>>(dWp, dWpTH, dWpTL, HSq, Dq);
    tconv<<<dim3(Dq/32, Dq/32, 1), tb>>>(dWo, dWoTH, dWoTL, Dq, Dq);
    tconv<<<dim3(FFq/32, Dq/32, 1), tb>>>(fW1, fW1TH, nullptr, Dq, FFq);
    tconv<<<dim3(Dq/32, FFq/32, 1), tb>>>(fW2, fW2TH, nullptr, FFq, Dq);

    // q,k (3-product: feeds softmax amplification), v (2-product)
    gemm_tc<3><<<dim3(4,64,Hq), 256, SMEMT>>>(srcH, srcL, WqTH, WqTL, mbq, nullptr, qH, qL,
        Dq, HSq, 1, 0,0, HSq,0, BTHS,0, HSq, 1.0f, 0, 0);
    gemm_tc<3><<<dim3(4,64,Hq), 256, SMEMT>>>(srcH, srcL, WkTH, WkTL, mbk, nullptr, kH, kL,
        Dq, HSq, 1, 0,0, HSq,0, BTHS,0, HSq, 1.0f, 0, 0);
    gemm_tc<2><<<dim3(4,64,Hq), 256, SMEMT>>>(srcH, srcL, WvTH, WvTL, nullptr, v, nullptr, nullptr,
        Dq, HSq, 1, 0,0, HSq,0, BTHS,0, 0, 1.0f, 0, 0);
    tconv<<<dim3(HSq/32, Tq/32, Hq*Bq), tb>>>(v, vTH, vTL, Tq, HSq);
    // scores: per (h,b), [1024,1024] = q @ k^T * 32 ; 3-product, causal block-skip
    gemm_tc<3><<<dim3(4,8,Hq*Bq), 256, SMEMT>>>(qH, qL, kH, kL, nullptr, w, nullptr, nullptr,
        HSq, Tq, Bq, BT,Tq, BT,Tq, BTT,TT, 0, 32.0f, 0, 1);
    softmax_causal<<<Hq*Bq*Tq, 256>>>(w, aH, aL);
    // o = a @ vT^T : per (h,b); 2-product, K truncated at diagonal
    gemm_tc<2><<<dim3(4,8,Hq*Bq), 256, SMEMT>>>(aH, aL, vTH, vTL, nullptr, ocat, nullptr, nullptr,
        Tq, Dq, Bq, Bq*Tq,Tq, Bq*HSq,HSq, (long)HSq,TD, 0, 1.0f, 0, 2);
    resln<<<BT, 256>>>(src, ocat, g1, b1, srcA, srcAH, srcAL, 0);
    // wp = att @ dWp^T : per head [8192,4096]
    gemm_tc<2><<<dim3(16,64,Hq), 256, SMEMT>>>(attH, attL, dWpTH, dWpTL, dbp, nullptr, wpH, wpL,
        HSq, Dq, 1, 0,0, Dq,0, BTD,0, Dq, 1.0f, 0, 0);
    // o2 = wp @ srcA^T : per (h,b), [1024,1024], K=4096
    gemm_tc<2><<<dim3(4,8,Hq*Bq), 256, SMEMT>>>(wpH, wpL, srcAH, srcAL, nullptr, nullptr, o2H, o2L,
        Dq, Dq, Bq, BT,Tq, 0,Tq, (long)Tq,TD, 0, 1.0f, 0, 0);
    // o3 = o2 @ dWo^T
    gemm_tc<2><<<dim3(16,64,1), 256, SMEMT>>>(o2H, o2L, dWoTH, dWoTL, dbo, o3, nullptr, nullptr,
        Dq, Dq, 1, 0,0, 0,0, 0,0, 0, 1.0f, 0, 0);
    resln<<<BT, 256>>>(srcA, o3, g1, b1, trgf, nullptr, nullptr, 0);
    resln<<<BT, 256>>>(trgf, nullptr, g2, b2, nullptr, ln2H, nullptr, 1);
    // h1 = gelu(ln2 @ fW1^T + fb1)  -- 1-product (error diluted ~70x by final LN)
    gemm_tc<1><<<dim3(80,64,1), 256, SMEMT>>>(ln2H, nullptr, fW1TH, nullptr, fb1, nullptr, h1H, nullptr,
        Dq, FFq, 1, 0,0, 0,0, 0,0, 0, 1.0f, 1, 0);
    // ff = h1 @ fW2^T + fb2  -- 1-product
    gemm_tc<1><<<dim3(16,64,1), 256, SMEMT>>>(h1H, nullptr, fW2TH, nullptr, fb2, ff, nullptr, nullptr,
        FFq, Dq, 1, 0,0, 0,0, 0,0, 0, 1.0f, 0, 0);
    resln<<<BT, 256>>>(trgf, ff, g2, b2, out, nullptr, nullptr, 1);
}

// round 9
// speedup vs baseline: 1.8242x; 1.0324x over previous
#include <cuda_runtime.h>
#include <cuda_fp16.h>
#include <math.h>
#include <stdint.h>

typedef __half hf;

#define Bq 8
#define Tq 1024
#define Dq 4096
#define Hq 4
#define HSq 1024
#define BT 8192
#define FFq 20480

// ----------------------------- scratch --------------------------------------
__device__ hf g_srcH[(size_t)BT*Dq], g_srcL[(size_t)BT*Dq];
__device__ hf g_attH[(size_t)BT*HSq], g_attL[(size_t)BT*HSq];
__device__ hf g_WqTH[(size_t)Hq*HSq*Dq], g_WqTL[(size_t)Hq*HSq*Dq];
__device__ hf g_WkTH[(size_t)Hq*HSq*Dq], g_WkTL[(size_t)Hq*HSq*Dq];
__device__ hf g_WvTH[(size_t)Hq*HSq*Dq], g_WvTL[(size_t)Hq*HSq*Dq];
__device__ hf g_qH[(size_t)Hq*BT*HSq], g_qL[(size_t)Hq*BT*HSq];
__device__ hf g_kH[(size_t)Hq*BT*HSq], g_kL[(size_t)Hq*BT*HSq];
__device__ float g_v[(size_t)Hq*BT*HSq];
__device__ hf g_vTH[(size_t)Hq*BT*HSq], g_vTL[(size_t)Hq*BT*HSq];
__device__ float g_w[(size_t)Hq*Bq*Tq*Tq];
__device__ hf g_aH[(size_t)Hq*Bq*Tq*Tq], g_aL[(size_t)Hq*Bq*Tq*Tq];
__device__ float g_ocat[(size_t)BT*Dq];
__device__ float g_srcA[(size_t)BT*Dq];
__device__ hf g_srcAH[(size_t)BT*Dq], g_srcAL[(size_t)BT*Dq];
__device__ hf g_dWpTH[(size_t)Hq*Dq*HSq], g_dWpTL[(size_t)Hq*Dq*HSq];
__device__ hf g_wpH[(size_t)Hq*BT*Dq], g_wpL[(size_t)Hq*BT*Dq];
__device__ hf g_o2H[(size_t)BT*Dq], g_o2L[(size_t)BT*Dq];
__device__ hf g_dWoTH[(size_t)Dq*Dq], g_dWoTL[(size_t)Dq*Dq];
__device__ float g_o3[(size_t)BT*Dq];
__device__ float g_trgf[(size_t)BT*Dq];
__device__ hf g_ln2H[(size_t)BT*Dq];
__device__ hf g_fW1TH[(size_t)FFq*Dq];
__device__ hf g_h1H[(size_t)BT*FFq];
__device__ hf g_fW2TH[(size_t)Dq*FFq];
__device__ float g_ff[(size_t)BT*Dq];

// ----------------------------- helpers --------------------------------------
__device__ __forceinline__ uint32_t smem_u32(const void* p) {
    uint32_t a;
    asm("{ .reg .u64 t; cvta.to.shared.u64 t, %1; cvt.u32.u64 %0, t; }" : "=r"(a) : "l"(p));
    return a;
}
#define CPA16(dst, src) asm volatile("cp.async.cg.shared.global [%0], [%1], 16;" :: "r"((uint32_t)(dst)), "l"(src) : "memory")
#define CP_COMMIT()     asm volatile("cp.async.commit_group;" ::: "memory")
#define CP_WAIT1()      asm volatile("cp.async.wait_group 1;" ::: "memory")
#define LDSM4(r, a) asm volatile("ldmatrix.sync.aligned.m8n8.x4.shared.b16 {%0,%1,%2,%3}, [%4];" \
    : "=r"((r)[0]), "=r"((r)[1]), "=r"((r)[2]), "=r"((r)[3]) : "r"(a))
__device__ __forceinline__ void mma16816(float* d, const uint32_t* a, uint32_t b0, uint32_t b1) {
    asm volatile("mma.sync.aligned.m16n8k16.row.col.f32.f16.f16.f32 "
        "{%0,%1,%2,%3}, {%4,%5,%6,%7}, {%8,%9}, {%0,%1,%2,%3};"
        : "+f"(d[0]), "+f"(d[1]), "+f"(d[2]), "+f"(d[3])
        : "r"(a[0]), "r"(a[1]), "r"(a[2]), "r"(a[3]), "r"(b0), "r"(b1));
}
__device__ __forceinline__ void mma16816h(uint32_t* d, const uint32_t* a, uint32_t b0, uint32_t b1) {
    asm volatile("mma.sync.aligned.m16n8k16.row.col.f16.f16.f16.f16 "
        "{%0,%1}, {%2,%3,%4,%5}, {%6,%7}, {%0,%1};"
        : "+r"(d[0]), "+r"(d[1])
        : "r"(a[0]), "r"(a[1]), "r"(a[2]), "r"(a[3]), "r"(b0), "r"(b1));
}
__device__ __forceinline__ float gelu_exact(float x) { return 0.5f*x*(1.0f+erff(x*0.70710678118654752440f)); }
__device__ __forceinline__ void split_hf(float x, hf& h, hf& l) {
    h = __float2half(x); l = __float2half(x - __half2float(h));
}

#define SST   98304      // stage: Ah 16K | Al 16K | Bh 32K | Bl 32K
#define SMEMT 196608
#define SSTF  49152      // ff stage: Ah 16K | Bh 32K
#define SMEMF 98304

// ====== mma.sync split-fp16 GEMM: C = act(alpha*A@B^T + bias) ================
// NPROD=3: Ah*Bh+Al*Bh+Ah*Bl (~2^-22). NPROD=2: Ah*Bh+Al*Bh (~2.8e-4).
// causal: 0 none; 1 skip blocks above diagonal; 2 truncate K at diagonal.
// CTA tile 128x256, 8 warps (warp tile 64x64), K-chunk 64, cp.async 2-stage.
template<int NPROD>
__global__ void __launch_bounds__(256, 1)
gemm_tc(const hf* __restrict__ Ah, const hf* __restrict__ Al,
        const hf* __restrict__ Bh, const hf* __restrict__ Bl,
        const float* __restrict__ bias, float* __restrict__ C,
        hf* __restrict__ Ch, hf* __restrict__ Cl,
        int K, int ldc, int batch2, int aR1, int aR2, int bR1, int bR2,
        long sC1, long sC2, long sB1, float alpha, int act, int causal)
{
    if (causal == 1 && (int)blockIdx.x * 256 > (int)blockIdx.y * 128 + 127) return;
    extern __shared__ __align__(1024) char sm[];
    uint32_t sb = smem_u32(sm);
    int tid = threadIdx.x, wid = tid >> 5, lane = tid & 31;
    int z = blockIdx.z, z1 = z / batch2, z2 = z % batch2;
    long aOff = (long)z1*aR1 + (long)z2*aR2 + blockIdx.y*128;
    long bOff = (long)z1*bR1 + (long)z2*bR2 + blockIdx.x*256;
    int warp_m = (wid & 1) * 64, warp_n = (wid >> 1) * 64;

    float acc[4][8][4];
#pragma unroll
    for (int mt = 0; mt < 4; mt++)
#pragma unroll
        for (int nt = 0; nt < 8; nt++)
#pragma unroll
            for (int r = 0; r < 4; r++) acc[mt][nt][r] = 0.f;

    int nkt = K >> 6;
    if (causal == 2) { int lim = 2 * (int)blockIdx.y + 2; if (lim < nkt) nkt = lim; }

    auto load_stage = [&](int s, int kt) {
        uint32_t base = sb + s * SST;
        long kb = (long)kt * 64;
#pragma unroll
        for (int it = 0; it < 4; it++) {
            int idx = tid + it * 256;
            int r = idx >> 3, c = idx & 7;
            uint32_t off = (uint32_t)(r * 128 + ((c ^ (r & 7)) << 4));
            long gi = (aOff + r) * (long)K + kb + c * 8;
            CPA16(base + off, Ah + gi);
            if (NPROD >= 2) CPA16(base + 16384 + off, Al + gi);
        }
#pragma unroll
        for (int it = 0; it < 8; it++) {
            int idx = tid + it * 256;
            int r = idx >> 3, c = idx & 7;
            uint32_t off = (uint32_t)(r * 128 + ((c ^ (r & 7)) << 4));
            long gi = (bOff + r) * (long)K + kb + c * 8;
            CPA16(base + 32768 + off, Bh + gi);
            if (NPROD == 3) CPA16(base + 65536 + off, Bl + gi);
        }
    };

    load_stage(0, 0);
    CP_COMMIT();

    for (int kt = 0; kt < nkt; kt++) {
        int s = kt & 1;
        if (kt + 1 < nkt) load_stage(s ^ 1, kt + 1);
        CP_COMMIT();
        CP_WAIT1();
        __syncthreads();

        uint32_t sA_h = sb + s * SST, sA_l = sA_h + 16384;
        uint32_t sB_h = sA_h + 32768, sB_l = sA_h + 65536;
#pragma unroll
        for (int ks = 0; ks < 4; ks++) {
            uint32_t ah[4][4], al[4][4];
#pragma unroll
            for (int mt = 0; mt < 4; mt++) {
                int row = warp_m + mt * 16 + (lane & 15);
                int c16 = ks * 2 + (lane >> 4);
                uint32_t off = (uint32_t)(row * 128 + ((c16 ^ (row & 7)) << 4));
                LDSM4(ah[mt], sA_h + off);
                if (NPROD >= 2) LDSM4(al[mt], sA_l + off);
            }
#pragma unroll
            for (int p = 0; p < 4; p++) {
                int row = warp_n + p * 16 + ((lane >> 4) << 3) + (lane & 7);
                int c16 = ks * 2 + ((lane >> 3) & 1);
                uint32_t off = (uint32_t)(row * 128 + ((c16 ^ (row & 7)) << 4));
                uint32_t bh[4];
                LDSM4(bh, sB_h + off);
#pragma unroll
                for (int mt = 0; mt < 4; mt++) {
                    mma16816(acc[mt][2*p],   ah[mt], bh[0], bh[1]);
                    mma16816(acc[mt][2*p+1], ah[mt], bh[2], bh[3]);
                }
                if (NPROD >= 2) {
#pragma unroll
                    for (int mt = 0; mt < 4; mt++) {
                        mma16816(acc[mt][2*p],   al[mt], bh[0], bh[1]);
                        mma16816(acc[mt][2*p+1], al[mt], bh[2], bh[3]);
                    }
                }
                if (NPROD == 3) {
                    uint32_t bl[4];
                    LDSM4(bl, sB_l + off);
#pragma unroll
                    for (int mt = 0; mt < 4; mt++) {
                        mma16816(acc[mt][2*p],   ah[mt], bl[0], bl[1]);
                        mma16816(acc[mt][2*p+1], ah[mt], bl[2], bl[3]);
                    }
                }
            }
        }
        __syncthreads();
    }

    // ---- epilogue ----
    float* Cp = C ? C + z1*sC1 + z2*sC2 : nullptr;
    hf *Chp = Ch ? Ch + z1*sC1 + z2*sC2 : nullptr;
    hf *Clp = Cl ? Cl + z1*sC1 + z2*sC2 : nullptr;
    const float* bp = bias ? bias + z1*sB1 : nullptr;
    int rowBase = blockIdx.y*128 + warp_m + (lane >> 2);
    int colBase = blockIdx.x*256 + warp_n + (lane & 3) * 2;
#pragma unroll
    for (int mt = 0; mt < 4; mt++) {
#pragma unroll
        for (int nt = 0; nt < 8; nt++) {
#pragma unroll
            for (int hh = 0; hh < 2; hh++) {
                int row = rowBase + mt * 16 + hh * 8;
                int col = colBase + nt * 8;
                float x0 = acc[mt][nt][hh*2]     * alpha;
                float x1 = acc[mt][nt][hh*2 + 1] * alpha;
                if (bp) { x0 += bp[col]; x1 += bp[col + 1]; }
                if (act) { x0 = gelu_exact(x0); x1 = gelu_exact(x1); }
                long o = (long)row * ldc + col;
                if (Cp) *(float2*)(Cp + o) = make_float2(x0, x1);
                if (Chp) {
                    hf h0, l0, h1, l1;
                    split_hf(x0, h0, l0); split_hf(x1, h1, l1);
                    *(__half2*)(Chp + o) = __halves2half2(h0, h1);
                    if (Clp) *(__half2*)(Clp + o) = __halves2half2(l0, l1);
                }
            }
        }
    }
}

// ====== FF GEMM: fp16-accumulate, 1-product (error diluted by final LN) ======
// C = act(A@B^T + bias). Compact smem (48KB/stage) -> 2 CTAs/SM.
__global__ void __launch_bounds__(256, 2)
gemm_ff(const hf* __restrict__ A, const hf* __restrict__ B,
        const float* __restrict__ bias, float* __restrict__ C, hf* __restrict__ Ch,
        int K, int ldc, int act)
{
    extern __shared__ __align__(1024) char sm[];
    uint32_t sb = smem_u32(sm);
    int tid = threadIdx.x, wid = tid >> 5, lane = tid & 31;
    long aOff = blockIdx.y * 128;
    long bOff = blockIdx.x * 256;
    int warp_m = (wid & 1) * 64, warp_n = (wid >> 1) * 64;

    uint32_t hacc[4][8][2];
#pragma unroll
    for (int mt = 0; mt < 4; mt++)
#pragma unroll
        for (int nt = 0; nt < 8; nt++) { hacc[mt][nt][0] = 0u; hacc[mt][nt][1] = 0u; }

    int nkt = K >> 6;
    auto load_stage = [&](int s, int kt) {
        uint32_t base = sb + s * SSTF;
        long kb = (long)kt * 64;
#pragma unroll
        for (int it = 0; it < 4; it++) {
            int idx = tid + it * 256;
            int r = idx >> 3, c = idx & 7;
            uint32_t off = (uint32_t)(r * 128 + ((c ^ (r & 7)) << 4));
            CPA16(base + off, A + (aOff + r) * (long)K + kb + c * 8);
        }
#pragma unroll
        for (int it = 0; it < 8; it++) {
            int idx = tid + it * 256;
            int r = idx >> 3, c = idx & 7;
            uint32_t off = (uint32_t)(r * 128 + ((c ^ (r & 7)) << 4));
            CPA16(base + 16384 + off, B + (bOff + r) * (long)K + kb + c * 8);
        }
    };

    load_stage(0, 0);
    CP_COMMIT();

    for (int kt = 0; kt < nkt; kt++) {
        int s = kt & 1;
        if (kt + 1 < nkt) load_stage(s ^ 1, kt + 1);
        CP_COMMIT();
        CP_WAIT1();
        __syncthreads();

        uint32_t sA = sb + s * SSTF, sB = sA + 16384;
#pragma unroll
        for (int ks = 0; ks < 4; ks++) {
            uint32_t ah[4][4];
#pragma unroll
            for (int mt = 0; mt < 4; mt++) {
                int row = warp_m + mt * 16 + (lane & 15);
                int c16 = ks * 2 + (lane >> 4);
                uint32_t off = (uint32_t)(row * 128 + ((c16 ^ (row & 7)) << 4));
                LDSM4(ah[mt], sA + off);
            }
#pragma unroll
            for (int p = 0; p < 4; p++) {
                int row = warp_n + p * 16 + ((lane >> 4) << 3) + (lane & 7);
                int c16 = ks * 2 + ((lane >> 3) & 1);
                uint32_t off = (uint32_t)(row * 128 + ((c16 ^ (row & 7)) << 4));
                uint32_t bh[4];
                LDSM4(bh, sB + off);
#pragma unroll
                for (int mt = 0; mt < 4; mt++) {
                    mma16816h(hacc[mt][2*p],   ah[mt], bh[0], bh[1]);
                    mma16816h(hacc[mt][2*p+1], ah[mt], bh[2], bh[3]);
                }
            }
        }
        __syncthreads();
    }

    // ---- epilogue (convert fp16 acc -> fp32, bias, act) ----
    int rowBase = blockIdx.y*128 + warp_m + (lane >> 2);
    int colBase = blockIdx.x*256 + warp_n + (lane & 3) * 2;
#pragma unroll
    for (int mt = 0; mt < 4; mt++) {
#pragma unroll
        for (int nt = 0; nt < 8; nt++) {
#pragma unroll
            for (int hh = 0; hh < 2; hh++) {
                int row = rowBase + mt * 16 + hh * 8;
                int col = colBase + nt * 8;
                __half2 hv = *(__half2*)&hacc[mt][nt][hh];
                float x0 = __low2float(hv), x1 = __high2float(hv);
                if (bias) { x0 += bias[col]; x1 += bias[col + 1]; }
                if (act) { x0 = gelu_exact(x0); x1 = gelu_exact(x1); }
                long o = (long)row * ldc + col;
                if (C) *(float2*)(C + o) = make_float2(x0, x1);
                if (Ch) *(__half2*)(Ch + o) = __halves2half2(__float2half(x0), __float2half(x1));
            }
        }
    }
}

// ---------------- fp32 -> (hi,lo) fp16 --------------------------------------
__global__ void conv_hl(const float4* __restrict__ x, hf* __restrict__ h, hf* __restrict__ l) {
    long i = (long)blockIdx.x*256 + threadIdx.x;
    float4 v = x[i];
    hf h0,l0,h1,l1,h2,l2,h3,l3;
    split_hf(v.x,h0,l0); split_hf(v.y,h1,l1); split_hf(v.z,h2,l2); split_hf(v.w,h3,l3);
    __half2* hp = (__half2*)(h + 4*i);
    __half2* lp = (__half2*)(l + 4*i);
    hp[0]=__halves2half2(h0,h1); hp[1]=__halves2half2(h2,h3);
    lp[0]=__halves2half2(l0,l1); lp[1]=__halves2half2(l2,l3);
}

// ------------- transpose+split: in[z][R][Cc] -> out[z][Cc][R] ----------------
__global__ void tconv(const float* __restrict__ in, hf* __restrict__ oh, hf* __restrict__ ol, int R, int Cc) {
    __shared__ float t[32][33];
    long base = (long)blockIdx.z * R * Cc;
    int c0 = blockIdx.x*32, r0 = blockIdx.y*32;
#pragma unroll
    for (int i = 0; i < 4; i++)
        t[threadIdx.y + i*8][threadIdx.x] = in[base + (long)(r0 + threadIdx.y + i*8)*Cc + c0 + threadIdx.x];
    __syncthreads();
#pragma unroll
    for (int i = 0; i < 4; i++) {
        int c = c0 + threadIdx.y + i*8, r = r0 + threadIdx.x;
        hf h, l; split_hf(t[threadIdx.x][threadIdx.y + i*8], h, l);
        long o = base + (long)c*R + r;
        oh[o] = h;
        if (ol) ol[o] = l;
    }
}

// ------------------ causal softmax -> (hi,lo) fp16 ---------------------------
__global__ void softmax_causal(const float* __restrict__ w, hf* __restrict__ aH, hf* __restrict__ aL) {
    long row = blockIdx.x;
    int t = (int)(row % Tq), tid = threadIdx.x;
    const float* p = w + row*(long)Tq;
    __shared__ float red[256];
    float vals[4], vmax = -1e30f;
#pragma unroll
    for (int i = 0; i < 4; i++) {
        int j = tid + i*256; float x = p[j]; vals[i] = x;
        if (j <= t && x > vmax) vmax = x;
    }
    red[tid] = vmax; __syncthreads();
    for (int s = 128; s > 0; s >>= 1) { if (tid < s) red[tid] = fmaxf(red[tid], red[tid+s]); __syncthreads(); }
    vmax = red[0]; __syncthreads();
    float sum = 0.f;
#pragma unroll
    for (int i = 0; i < 4; i++) {
        int j = tid + i*256;
        float e = (j <= t) ? expf(vals[i] - vmax) : 0.f;
        vals[i] = e; sum += e;
    }
    red[tid] = sum; __syncthreads();
    for (int s = 128; s > 0; s >>= 1) { if (tid < s) red[tid] += red[tid+s]; __syncthreads(); }
    float inv = 1.f / red[0];
#pragma unroll
    for (int i = 0; i < 4; i++) {
        hf h, l; split_hf(vals[i]*inv, h, l);
        long o = row*(long)Tq + tid + i*256;
        aH[o] = h; aL[o] = l;
    }
}

// --- residual+LN: t = x(+y); out = ln_only ? ln(t) : t+ln(t); optional hi/lo -
__global__ void resln(const float* __restrict__ x, const float* __restrict__ y,
                      const float* __restrict__ g, const float* __restrict__ b,
                      float* __restrict__ out, hf* __restrict__ oh, hf* __restrict__ ol, int ln_only) {
    long row = blockIdx.x;
    int tid = threadIdx.x;
    const float* px = x + row*(long)Dq;
    const float* py = y ? y + row*(long)Dq : nullptr;
    __shared__ float sh[Dq];
    __shared__ float red[256];
    float ls = 0.f;
    for (int i = tid; i < Dq; i += 256) { float t = px[i] + (py ? py[i] : 0.f); sh[i] = t; ls += t; }
    red[tid] = ls; __syncthreads();
    for (int s = 128; s > 0; s >>= 1) { if (tid < s) red[tid] += red[tid+s]; __syncthreads(); }
    float mean = red[0] * (1.0f/Dq); __syncthreads();
    float lv = 0.f;
    for (int i = tid; i < Dq; i += 256) { float d = sh[i]-mean; lv += d*d; }
    red[tid] = lv; __syncthreads();
    for (int s = 128; s > 0; s >>= 1) { if (tid < s) red[tid] += red[tid+s]; __syncthreads(); }
    float rstd = rsqrtf(red[0]*(1.0f/Dq) + 1e-5f);
    for (int i = tid; i < Dq; i += 256) {
        float t = sh[i];
        float l = (t - mean)*rstd*g[i] + b[i];
        float o = ln_only ? l : t + l;
        long oi = row*(long)Dq + i;
        if (out) out[oi] = o;
        if (oh) {
            hf hh, ll; split_hf(o, hh, ll);
            oh[oi] = hh;
            if (ol) ol[oi] = ll;
        }
    }
}

// -----------------------------------------------------------------------------
extern "C" void kernel_launch(void* const* d_in, const int* in_sizes, int n_in,
                              void* d_out, int out_size)
{
    const float* src=(const float*)d_in[0]; const float* att=(const float*)d_in[1];
    const float* mWq=(const float*)d_in[2]; const float* mbq=(const float*)d_in[3];
    const float* mWk=(const float*)d_in[4]; const float* mbk=(const float*)d_in[5];
    const float* mWv=(const float*)d_in[6]; const float* dWp=(const float*)d_in[7];
    const float* dbp=(const float*)d_in[8]; const float* dWo=(const float*)d_in[9];
    const float* dbo=(const float*)d_in[10]; const float* fW1=(const float*)d_in[11];
    const float* fb1=(const float*)d_in[12]; const float* fW2=(const float*)d_in[13];
    const float* fb2=(const float*)d_in[14]; const float* g1=(const float*)d_in[15];
    const float* b1=(const float*)d_in[16]; const float* g2=(const float*)d_in[17];
    const float* b2=(const float*)d_in[18];
    float* out = (float*)d_out;

#define SYM(T,p,s) T p; cudaGetSymbolAddress((void**)&p, s)
    SYM(hf*,srcH,g_srcH); SYM(hf*,srcL,g_srcL); SYM(hf*,attH,g_attH); SYM(hf*,attL,g_attL);
    SYM(hf*,WqTH,g_WqTH); SYM(hf*,WqTL,g_WqTL); SYM(hf*,WkTH,g_WkTH); SYM(hf*,WkTL,g_WkTL);
    SYM(hf*,WvTH,g_WvTH); SYM(hf*,WvTL,g_WvTL);
    SYM(hf*,qH,g_qH); SYM(hf*,qL,g_qL); SYM(hf*,kH,g_kH); SYM(hf*,kL,g_kL);
    SYM(float*,v,g_v); SYM(hf*,vTH,g_vTH); SYM(hf*,vTL,g_vTL);
    SYM(float*,w,g_w); SYM(hf*,aH,g_aH); SYM(hf*,aL,g_aL);
    SYM(float*,ocat,g_ocat); SYM(float*,srcA,g_srcA); SYM(hf*,srcAH,g_srcAH); SYM(hf*,srcAL,g_srcAL);
    SYM(hf*,dWpTH,g_dWpTH); SYM(hf*,dWpTL,g_dWpTL); SYM(hf*,wpH,g_wpH); SYM(hf*,wpL,g_wpL);
    SYM(hf*,o2H,g_o2H); SYM(hf*,o2L,g_o2L); SYM(hf*,dWoTH,g_dWoTH); SYM(hf*,dWoTL,g_dWoTL);
    SYM(float*,o3,g_o3); SYM(float*,trgf,g_trgf); SYM(hf*,ln2H,g_ln2H);
    SYM(hf*,fW1TH,g_fW1TH); SYM(hf*,h1H,g_h1H);
    SYM(hf*,fW2TH,g_fW2TH); SYM(float*,ff,g_ff);

    cudaFuncSetAttribute(gemm_tc<2>, cudaFuncAttributeMaxDynamicSharedMemorySize, SMEMT);
    cudaFuncSetAttribute(gemm_tc<3>, cudaFuncAttributeMaxDynamicSharedMemorySize, SMEMT);
    cudaFuncSetAttribute(gemm_ff,    cudaFuncAttributeMaxDynamicSharedMemorySize, SMEMF);
    dim3 tb(32, 8);
    const long TT=(long)Tq*Tq, TD=(long)Tq*Dq, BTD=(long)BT*Dq, BTHS=(long)BT*HSq, BTT=(long)Bq*Tq*Tq;

    // --- launch order arranged so ncu (-s 5 -c 1) captures a GEMM at idx 5 ---
    conv_hl<<<BTD/1024, 256>>>((const float4*)src, srcH, srcL);                 // 0
    tconv<<<dim3(HSq/32, Dq/32, Hq), tb>>>(mWq, WqTH, WqTL, Dq, HSq);           // 1
    tconv<<<dim3(HSq/32, Dq/32, Hq), tb>>>(mWk, WkTH, WkTL, Dq, HSq);           // 2
    tconv<<<dim3(HSq/32, Dq/32, Hq), tb>>>(mWv, WvTH, WvTL, Dq, HSq);           // 3
    gemm_tc<3><<<dim3(4,64,Hq), 256, SMEMT>>>(srcH, srcL, WqTH, WqTL, mbq, nullptr, qH, qL,
        Dq, HSq, 1, 0,0, HSq,0, BTHS,0, HSq, 1.0f, 0, 0);                       // 4
    gemm_tc<3><<<dim3(4,64,Hq), 256, SMEMT>>>(srcH, srcL, WkTH, WkTL, mbk, nullptr, kH, kL,
        Dq, HSq, 1, 0,0, HSq,0, BTHS,0, HSq, 1.0f, 0, 0);                       // 5 <- profiled
    gemm_tc<2><<<dim3(4,64,Hq), 256, SMEMT>>>(srcH, srcL, WvTH, WvTL, nullptr, v, nullptr, nullptr,
        Dq, HSq, 1, 0,0, HSq,0, BTHS,0, 0, 1.0f, 0, 0);                         // 6
    conv_hl<<<BTHS/1024, 256>>>((const float4*)att, attH, attL);
    tconv<<<dim3(Dq/32, HSq/32, Hq), tb>>>(dWp, dWpTH, dWpTL, HSq, Dq);
    tconv<<<dim3(Dq/32, Dq/32, 1), tb>>>(dWo, dWoTH, dWoTL, Dq, Dq);
    tconv<<<dim3(FFq/32, Dq/32, 1), tb>>>(fW1, fW1TH, nullptr, Dq, FFq);
    tconv<<<dim3(Dq/32, FFq/32, 1), tb>>>(fW2, fW2TH, nullptr, FFq, Dq);
    tconv<<<dim3(HSq/32, Tq/32, Hq*Bq), tb>>>(v, vTH, vTL, Tq, HSq);

    // scores: per (h,b), [1024,1024] = q @ k^T * 32 ; 3-product, causal block-skip
    gemm_tc<3><<<dim3(4,8,Hq*Bq), 256, SMEMT>>>(qH, qL, kH, kL, nullptr, w, nullptr, nullptr,
        HSq, Tq, Bq, BT,Tq, BT,Tq, BTT,TT, 0, 32.0f, 0, 1);
    softmax_causal<<<Hq*Bq*Tq, 256>>>(w, aH, aL);
    // o = a @ vT^T : per (h,b); 2-product, K truncated at diagonal
    gemm_tc<2><<<dim3(4,8,Hq*Bq), 256, SMEMT>>>(aH, aL, vTH, vTL, nullptr, ocat, nullptr, nullptr,
        Tq, Dq, Bq, Bq*Tq,Tq, Bq*HSq,HSq, (long)HSq,TD, 0, 1.0f, 0, 2);
    resln<<<BT, 256>>>(src, ocat, g1, b1, srcA, srcAH, srcAL, 0);
    // wp = att @ dWp^T : per head [8192,4096]
    gemm_tc<2><<<dim3(16,64,Hq), 256, SMEMT>>>(attH, attL, dWpTH, dWpTL, dbp, nullptr, wpH, wpL,
        HSq, Dq, 1, 0,0, Dq,0, BTD,0, Dq, 1.0f, 0, 0);
    // o2 = wp @ srcA^T : per (h,b), [1024,1024], K=4096
    gemm_tc<2><<<dim3(4,8,Hq*Bq), 256, SMEMT>>>(wpH, wpL, srcAH, srcAL, nullptr, nullptr, o2H, o2L,
        Dq, Dq, Bq, BT,Tq, 0,Tq, (long)Tq,TD, 0, 1.0f, 0, 0);
    // o3 = o2 @ dWo^T
    gemm_tc<2><<<dim3(16,64,1), 256, SMEMT>>>(o2H, o2L, dWoTH, dWoTL, dbo, o3, nullptr, nullptr,
        Dq, Dq, 1, 0,0, 0,0, 0,0, 0, 1.0f, 0, 0);
    resln<<<BT, 256>>>(srcA, o3, g1, b1, trgf, nullptr, nullptr, 0);
    resln<<<BT, 256>>>(trgf, nullptr, g2, b2, nullptr, ln2H, nullptr, 1);
    // h1 = gelu(ln2 @ fW1^T + fb1)  -- fp16-accumulate (error diluted ~70x by final LN)
    gemm_ff<<<dim3(80,64,1), 256, SMEMF>>>(ln2H, fW1TH, fb1, nullptr, h1H, Dq, FFq, 1);
    // ff = h1 @ fW2^T + fb2  -- fp16-accumulate
    gemm_ff<<<dim3(16,64,1), 256, SMEMF>>>(h1H, fW2TH, fb2, ff, nullptr, FFq, Dq, 0);
    resln<<<BT, 256>>>(trgf, ff, g2, b2, out, nullptr, nullptr, 1);
}

// round 10
// speedup vs baseline: 2.1305x; 1.1679x over previous
#include <cuda_runtime.h>
#include <cuda_fp16.h>
#include <math.h>
#include <stdint.h>

typedef __half hf;

#define Bq 8
#define Tq 1024
#define Dq 4096
#define Hq 4
#define HSq 1024
#define BT 8192
#define FFq 20480

// ----------------------------- scratch --------------------------------------
__device__ hf g_srcH[(size_t)BT*Dq], g_srcL[(size_t)BT*Dq];
__device__ hf g_attH[(size_t)BT*HSq];
__device__ hf g_WqTH[(size_t)Hq*HSq*Dq], g_WqTL[(size_t)Hq*HSq*Dq];
__device__ hf g_WkTH[(size_t)Hq*HSq*Dq], g_WkTL[(size_t)Hq*HSq*Dq];
__device__ hf g_WvTH[(size_t)Hq*HSq*Dq];
__device__ hf g_qH[(size_t)Hq*BT*HSq], g_qL[(size_t)Hq*BT*HSq];
__device__ hf g_kH[(size_t)Hq*BT*HSq], g_kL[(size_t)Hq*BT*HSq];
__device__ float g_v[(size_t)Hq*BT*HSq];
__device__ hf g_vTH[(size_t)Hq*BT*HSq];
__device__ float g_w[(size_t)Hq*Bq*Tq*Tq];
__device__ hf g_aH[(size_t)Hq*Bq*Tq*Tq];
__device__ float g_ocat[(size_t)BT*Dq];
__device__ float g_srcA[(size_t)BT*Dq];
__device__ hf g_srcAH[(size_t)BT*Dq];
__device__ hf g_dWpTH[(size_t)Hq*Dq*HSq];
__device__ hf g_wpH[(size_t)Hq*BT*Dq];
__device__ hf g_o2H[(size_t)BT*Dq];
__device__ hf g_dWoTH[(size_t)Dq*Dq];
__device__ float g_o3[(size_t)BT*Dq];
__device__ float g_trgf[(size_t)BT*Dq];
__device__ hf g_ln2H[(size_t)BT*Dq];
__device__ hf g_fW1TH[(size_t)FFq*Dq];
__device__ hf g_h1H[(size_t)BT*FFq];
__device__ hf g_fW2TH[(size_t)Dq*FFq];
__device__ float g_ff[(size_t)BT*Dq];

// ----------------------------- helpers --------------------------------------
__device__ __forceinline__ uint32_t smem_u32(const void* p) {
    uint32_t a;
    asm("{ .reg .u64 t; cvta.to.shared.u64 t, %1; cvt.u32.u64 %0, t; }" : "=r"(a) : "l"(p));
    return a;
}
#define CPA16(dst, src) asm volatile("cp.async.cg.shared.global [%0], [%1], 16;" :: "r"((uint32_t)(dst)), "l"(src) : "memory")
#define CP_COMMIT()     asm volatile("cp.async.commit_group;" ::: "memory")
#define CP_WAIT1()      asm volatile("cp.async.wait_group 1;" ::: "memory")
#define LDSM4(r, a) asm volatile("ldmatrix.sync.aligned.m8n8.x4.shared.b16 {%0,%1,%2,%3}, [%4];" \
    : "=r"((r)[0]), "=r"((r)[1]), "=r"((r)[2]), "=r"((r)[3]) : "r"(a))
__device__ __forceinline__ void mma16816(float* d, const uint32_t* a, uint32_t b0, uint32_t b1) {
    asm volatile("mma.sync.aligned.m16n8k16.row.col.f32.f16.f16.f32 "
        "{%0,%1,%2,%3}, {%4,%5,%6,%7}, {%8,%9}, {%0,%1,%2,%3};"
        : "+f"(d[0]), "+f"(d[1]), "+f"(d[2]), "+f"(d[3])
        : "r"(a[0]), "r"(a[1]), "r"(a[2]), "r"(a[3]), "r"(b0), "r"(b1));
}
__device__ __forceinline__ void mma16816h(uint32_t* d, const uint32_t* a, uint32_t b0, uint32_t b1) {
    asm volatile("mma.sync.aligned.m16n8k16.row.col.f16.f16.f16.f16 "
        "{%0,%1}, {%2,%3,%4,%5}, {%6,%7}, {%0,%1};"
        : "+r"(d[0]), "+r"(d[1])
        : "r"(a[0]), "r"(a[1]), "r"(a[2]), "r"(a[3]), "r"(b0), "r"(b1));
}
__device__ __forceinline__ float gelu_exact(float x) { return 0.5f*x*(1.0f+erff(x*0.70710678118654752440f)); }
__device__ __forceinline__ void split_hf(float x, hf& h, hf& l) {
    h = __float2half(x); l = __float2half(x - __half2float(h));
}

#define SSTF  49152      // ff stage: Ah 16K | Bh 32K
#define SMEMF 98304

// ====== mma.sync split-fp16 GEMM: C = act(alpha*A@B^T + bias) ================
// fp32 accumulate. NPROD=3: Ah*Bh+Al*Bh+Ah*Bl (~2^-22 rel).
// NPROD=2: Ah*Bh+Al*Bh (~2.8e-4). NPROD=1: Ah*Bh (~4.9e-4, error-diluted paths).
// causal: 0 none; 1 skip blocks above diagonal; 2 truncate K at diagonal.
// CTA tile 128x256, 8 warps (warp tile 64x64), K-chunk 64, cp.async 2-stage.
template<int NPROD>
__global__ void __launch_bounds__(256, 1)
gemm_tc(const hf* __restrict__ Ah, const hf* __restrict__ Al,
        const hf* __restrict__ Bh, const hf* __restrict__ Bl,
        const float* __restrict__ bias, float* __restrict__ C,
        hf* __restrict__ Ch, hf* __restrict__ Cl,
        int K, int ldc, int batch2, int aR1, int aR2, int bR1, int bR2,
        long sC1, long sC2, long sB1, float alpha, int act, int causal)
{
    constexpr uint32_t B_OFF  = (NPROD >= 2) ? 32768u : 16384u;
    constexpr uint32_t BL_OFF = 65536u;
    constexpr uint32_t STAGE  = (NPROD == 3) ? 98304u : (NPROD == 2 ? 65536u : 49152u);

    if (causal == 1 && (int)blockIdx.x * 256 > (int)blockIdx.y * 128 + 127) return;
    extern __shared__ __align__(1024) char sm[];
    uint32_t sb = smem_u32(sm);
    int tid = threadIdx.x, wid = tid >> 5, lane = tid & 31;
    int z = blockIdx.z, z1 = z / batch2, z2 = z % batch2;
    long aOff = (long)z1*aR1 + (long)z2*aR2 + blockIdx.y*128;
    long bOff = (long)z1*bR1 + (long)z2*bR2 + blockIdx.x*256;
    int warp_m = (wid & 1) * 64, warp_n = (wid >> 1) * 64;

    float acc[4][8][4];
#pragma unroll
    for (int mt = 0; mt < 4; mt++)
#pragma unroll
        for (int nt = 0; nt < 8; nt++)
#pragma unroll
            for (int r = 0; r < 4; r++) acc[mt][nt][r] = 0.f;

    int nkt = K >> 6;
    if (causal == 2) { int lim = 2 * (int)blockIdx.y + 2; if (lim < nkt) nkt = lim; }

    auto load_stage = [&](int s, int kt) {
        uint32_t base = sb + s * STAGE;
        long kb = (long)kt * 64;
#pragma unroll
        for (int it = 0; it < 4; it++) {
            int idx = tid + it * 256;
            int r = idx >> 3, c = idx & 7;
            uint32_t off = (uint32_t)(r * 128 + ((c ^ (r & 7)) << 4));
            long gi = (aOff + r) * (long)K + kb + c * 8;
            CPA16(base + off, Ah + gi);
            if (NPROD >= 2) CPA16(base + 16384 + off, Al + gi);
        }
#pragma unroll
        for (int it = 0; it < 8; it++) {
            int idx = tid + it * 256;
            int r = idx >> 3, c = idx & 7;
            uint32_t off = (uint32_t)(r * 128 + ((c ^ (r & 7)) << 4));
            long gi = (bOff + r) * (long)K + kb + c * 8;
            CPA16(base + B_OFF + off, Bh + gi);
            if (NPROD == 3) CPA16(base + BL_OFF + off, Bl + gi);
        }
    };

    load_stage(0, 0);
    CP_COMMIT();

    for (int kt = 0; kt < nkt; kt++) {
        int s = kt & 1;
        if (kt + 1 < nkt) load_stage(s ^ 1, kt + 1);
        CP_COMMIT();
        CP_WAIT1();
        __syncthreads();

        uint32_t sA_h = sb + s * STAGE, sA_l = sA_h + 16384;
        uint32_t sB_h = sA_h + B_OFF, sB_l = sA_h + BL_OFF;
#pragma unroll
        for (int ks = 0; ks < 4; ks++) {
            uint32_t ah[4][4], al[4][4];
#pragma unroll
            for (int mt = 0; mt < 4; mt++) {
                int row = warp_m + mt * 16 + (lane & 15);
                int c16 = ks * 2 + (lane >> 4);
                uint32_t off = (uint32_t)(row * 128 + ((c16 ^ (row & 7)) << 4));
                LDSM4(ah[mt], sA_h + off);
                if (NPROD >= 2) LDSM4(al[mt], sA_l + off);
            }
#pragma unroll
            for (int p = 0; p < 4; p++) {
                int row = warp_n + p * 16 + ((lane >> 4) << 3) + (lane & 7);
                int c16 = ks * 2 + ((lane >> 3) & 1);
                uint32_t off = (uint32_t)(row * 128 + ((c16 ^ (row & 7)) << 4));
                uint32_t bh[4];
                LDSM4(bh, sB_h + off);
#pragma unroll
                for (int mt = 0; mt < 4; mt++) {
                    mma16816(acc[mt][2*p],   ah[mt], bh[0], bh[1]);
                    mma16816(acc[mt][2*p+1], ah[mt], bh[2], bh[3]);
                }
                if (NPROD >= 2) {
#pragma unroll
                    for (int mt = 0; mt < 4; mt++) {
                        mma16816(acc[mt][2*p],   al[mt], bh[0], bh[1]);
                        mma16816(acc[mt][2*p+1], al[mt], bh[2], bh[3]);
                    }
                }
                if (NPROD == 3) {
                    uint32_t bl[4];
                    LDSM4(bl, sB_l + off);
#pragma unroll
                    for (int mt = 0; mt < 4; mt++) {
                        mma16816(acc[mt][2*p],   ah[mt], bl[0], bl[1]);
                        mma16816(acc[mt][2*p+1], ah[mt], bl[2], bl[3]);
                    }
                }
            }
        }
        __syncthreads();
    }

    // ---- epilogue ----
    float* Cp = C ? C + z1*sC1 + z2*sC2 : nullptr;
    hf *Chp = Ch ? Ch + z1*sC1 + z2*sC2 : nullptr;
    hf *Clp = Cl ? Cl + z1*sC1 + z2*sC2 : nullptr;
    const float* bp = bias ? bias + z1*sB1 : nullptr;
    int rowBase = blockIdx.y*128 + warp_m + (lane >> 2);
    int colBase = blockIdx.x*256 + warp_n + (lane & 3) * 2;
#pragma unroll
    for (int mt = 0; mt < 4; mt++) {
#pragma unroll
        for (int nt = 0; nt < 8; nt++) {
#pragma unroll
            for (int hh = 0; hh < 2; hh++) {
                int row = rowBase + mt * 16 + hh * 8;
                int col = colBase + nt * 8;
                float x0 = acc[mt][nt][hh*2]     * alpha;
                float x1 = acc[mt][nt][hh*2 + 1] * alpha;
                if (bp) { x0 += bp[col]; x1 += bp[col + 1]; }
                if (act) { x0 = gelu_exact(x0); x1 = gelu_exact(x1); }
                long o = (long)row * ldc + col;
                if (Cp) *(float2*)(Cp + o) = make_float2(x0, x1);
                if (Chp) {
                    hf h0, l0, h1, l1;
                    split_hf(x0, h0, l0); split_hf(x1, h1, l1);
                    *(__half2*)(Chp + o) = __halves2half2(h0, h1);
                    if (Clp) *(__half2*)(Clp + o) = __halves2half2(l0, l1);
                }
            }
        }
    }
}

// ====== FF GEMM: fp16-accumulate, 1-product (error diluted by final LN) ======
__global__ void __launch_bounds__(256, 2)
gemm_ff(const hf* __restrict__ A, const hf* __restrict__ B,
        const float* __restrict__ bias, float* __restrict__ C, hf* __restrict__ Ch,
        int K, int ldc, int act)
{
    extern __shared__ __align__(1024) char sm[];
    uint32_t sb = smem_u32(sm);
    int tid = threadIdx.x, wid = tid >> 5, lane = tid & 31;
    long aOff = blockIdx.y * 128;
    long bOff = blockIdx.x * 256;
    int warp_m = (wid & 1) * 64, warp_n = (wid >> 1) * 64;

    uint32_t hacc[4][8][2];
#pragma unroll
    for (int mt = 0; mt < 4; mt++)
#pragma unroll
        for (int nt = 0; nt < 8; nt++) { hacc[mt][nt][0] = 0u; hacc[mt][nt][1] = 0u; }

    int nkt = K >> 6;
    auto load_stage = [&](int s, int kt) {
        uint32_t base = sb + s * SSTF;
        long kb = (long)kt * 64;
#pragma unroll
        for (int it = 0; it < 4; it++) {
            int idx = tid + it * 256;
            int r = idx >> 3, c = idx & 7;
            uint32_t off = (uint32_t)(r * 128 + ((c ^ (r & 7)) << 4));
            CPA16(base + off, A + (aOff + r) * (long)K + kb + c * 8);
        }
#pragma unroll
        for (int it = 0; it < 8; it++) {
            int idx = tid + it * 256;
            int r = idx >> 3, c = idx & 7;
            uint32_t off = (uint32_t)(r * 128 + ((c ^ (r & 7)) << 4));
            CPA16(base + 16384 + off, B + (bOff + r) * (long)K + kb + c * 8);
        }
    };

    load_stage(0, 0);
    CP_COMMIT();

    for (int kt = 0; kt < nkt; kt++) {
        int s = kt & 1;
        if (kt + 1 < nkt) load_stage(s ^ 1, kt + 1);
        CP_COMMIT();
        CP_WAIT1();
        __syncthreads();

        uint32_t sA = sb + s * SSTF, sB = sA + 16384;
#pragma unroll
        for (int ks = 0; ks < 4; ks++) {
            uint32_t ah[4][4];
#pragma unroll
            for (int mt = 0; mt < 4; mt++) {
                int row = warp_m + mt * 16 + (lane & 15);
                int c16 = ks * 2 + (lane >> 4);
                uint32_t off = (uint32_t)(row * 128 + ((c16 ^ (row & 7)) << 4));
                LDSM4(ah[mt], sA + off);
            }
#pragma unroll
            for (int p = 0; p < 4; p++) {
                int row = warp_n + p * 16 + ((lane >> 4) << 3) + (lane & 7);
                int c16 = ks * 2 + ((lane >> 3) & 1);
                uint32_t off = (uint32_t)(row * 128 + ((c16 ^ (row & 7)) << 4));
                uint32_t bh[4];
                LDSM4(bh, sB + off);
#pragma unroll
                for (int mt = 0; mt < 4; mt++) {
                    mma16816h(hacc[mt][2*p],   ah[mt], bh[0], bh[1]);
                    mma16816h(hacc[mt][2*p+1], ah[mt], bh[2], bh[3]);
                }
            }
        }
        __syncthreads();
    }

    int rowBase = blockIdx.y*128 + warp_m + (lane >> 2);
    int colBase = blockIdx.x*256 + warp_n + (lane & 3) * 2;
#pragma unroll
    for (int mt = 0; mt < 4; mt++) {
#pragma unroll
        for (int nt = 0; nt < 8; nt++) {
#pragma unroll
            for (int hh = 0; hh < 2; hh++) {
                int row = rowBase + mt * 16 + hh * 8;
                int col = colBase + nt * 8;
                __half2 hv = *(__half2*)&hacc[mt][nt][hh];
                float x0 = __low2float(hv), x1 = __high2float(hv);
                if (bias) { x0 += bias[col]; x1 += bias[col + 1]; }
                if (act) { x0 = gelu_exact(x0); x1 = gelu_exact(x1); }
                long o = (long)row * ldc + col;
                if (C) *(float2*)(C + o) = make_float2(x0, x1);
                if (Ch) *(__half2*)(Ch + o) = __halves2half2(__float2half(x0), __float2half(x1));
            }
        }
    }
}

// ---------------- fp32 -> (hi,lo) fp16 --------------------------------------
__global__ void conv_hl(const float4* __restrict__ x, hf* __restrict__ h, hf* __restrict__ l) {
    long i = (long)blockIdx.x*256 + threadIdx.x;
    float4 v = x[i];
    hf h0,l0,h1,l1,h2,l2,h3,l3;
    split_hf(v.x,h0,l0); split_hf(v.y,h1,l1); split_hf(v.z,h2,l2); split_hf(v.w,h3,l3);
    __half2* hp = (__half2*)(h + 4*i);
    hp[0]=__halves2half2(h0,h1); hp[1]=__halves2half2(h2,h3);
    if (l) {
        __half2* lp = (__half2*)(l + 4*i);
        lp[0]=__halves2half2(l0,l1); lp[1]=__halves2half2(l2,l3);
    }
}

// ------------- transpose+split: in[z][R][Cc] -> out[z][Cc][R] ----------------
__global__ void tconv(const float* __restrict__ in, hf* __restrict__ oh, hf* __restrict__ ol, int R, int Cc) {
    __shared__ float t[32][33];
    long base = (long)blockIdx.z * R * Cc;
    int c0 = blockIdx.x*32, r0 = blockIdx.y*32;
#pragma unroll
    for (int i = 0; i < 4; i++)
        t[threadIdx.y + i*8][threadIdx.x] = in[base + (long)(r0 + threadIdx.y + i*8)*Cc + c0 + threadIdx.x];
    __syncthreads();
#pragma unroll
    for (int i = 0; i < 4; i++) {
        int c = c0 + threadIdx.y + i*8, r = r0 + threadIdx.x;
        hf h, l; split_hf(t[threadIdx.x][threadIdx.y + i*8], h, l);
        long o = base + (long)c*R + r;
        oh[o] = h;
        if (ol) ol[o] = l;
    }
}

// ------------------ causal softmax -> fp16 (hi only) -------------------------
__global__ void softmax_causal(const float* __restrict__ w, hf* __restrict__ aH) {
    long row = blockIdx.x;
    int t = (int)(row % Tq), tid = threadIdx.x;
    const float* p = w + row*(long)Tq;
    __shared__ float red[256];
    float vals[4], vmax = -1e30f;
#pragma unroll
    for (int i = 0; i < 4; i++) {
        int j = tid + i*256; float x = p[j]; vals[i] = x;
        if (j <= t && x > vmax) vmax = x;
    }
    red[tid] = vmax; __syncthreads();
    for (int s = 128; s > 0; s >>= 1) { if (tid < s) red[tid] = fmaxf(red[tid], red[tid+s]); __syncthreads(); }
    vmax = red[0]; __syncthreads();
    float sum = 0.f;
#pragma unroll
    for (int i = 0; i < 4; i++) {
        int j = tid + i*256;
        float e = (j <= t) ? expf(vals[i] - vmax) : 0.f;
        vals[i] = e; sum += e;
    }
    red[tid] = sum; __syncthreads();
    for (int s = 128; s > 0; s >>= 1) { if (tid < s) red[tid] += red[tid+s]; __syncthreads(); }
    float inv = 1.f / red[0];
#pragma unroll
    for (int i = 0; i < 4; i++)
        aH[row*(long)Tq + tid + i*256] = __float2half(vals[i]*inv);
}

// --- residual+LN: t = x(+y); out = ln_only ? ln(t) : t+ln(t); optional hi/lo -
__global__ void resln(const float* __restrict__ x, const float* __restrict__ y,
                      const float* __restrict__ g, const float* __restrict__ b,
                      float* __restrict__ out, hf* __restrict__ oh, hf* __restrict__ ol, int ln_only) {
    long row = blockIdx.x;
    int tid = threadIdx.x;
    const float* px = x + row*(long)Dq;
    const float* py = y ? y + row*(long)Dq : nullptr;
    __shared__ float sh[Dq];
    __shared__ float red[256];
    float ls = 0.f;
    for (int i = tid; i < Dq; i += 256) { float t = px[i] + (py ? py[i] : 0.f); sh[i] = t; ls += t; }
    red[tid] = ls; __syncthreads();
    for (int s = 128; s > 0; s >>= 1) { if (tid < s) red[tid] += red[tid+s]; __syncthreads(); }
    float mean = red[0] * (1.0f/Dq); __syncthreads();
    float lv = 0.f;
    for (int i = tid; i < Dq; i += 256) { float d = sh[i]-mean; lv += d*d; }
    red[tid] = lv; __syncthreads();
    for (int s = 128; s > 0; s >>= 1) { if (tid < s) red[tid] += red[tid+s]; __syncthreads(); }
    float rstd = rsqrtf(red[0]*(1.0f/Dq) + 1e-5f);
    for (int i = tid; i < Dq; i += 256) {
        float t = sh[i];
        float l = (t - mean)*rstd*g[i] + b[i];
        float o = ln_only ? l : t + l;
        long oi = row*(long)Dq + i;
        if (out) out[oi] = o;
        if (oh) {
            hf hh, ll; split_hf(o, hh, ll);
            oh[oi] = hh;
            if (ol) ol[oi] = ll;
        }
    }
}

// -----------------------------------------------------------------------------
extern "C" void kernel_launch(void* const* d_in, const int* in_sizes, int n_in,
                              void* d_out, int out_size)
{
    const float* src=(const float*)d_in[0]; const float* att=(const float*)d_in[1];
    const float* mWq=(const float*)d_in[2]; const float* mbq=(const float*)d_in[3];
    const float* mWk=(const float*)d_in[4]; const float* mbk=(const float*)d_in[5];
    const float* mWv=(const float*)d_in[6]; const float* dWp=(const float*)d_in[7];
    const float* dbp=(const float*)d_in[8]; const float* dWo=(const float*)d_in[9];
    const float* dbo=(const float*)d_in[10]; const float* fW1=(const float*)d_in[11];
    const float* fb1=(const float*)d_in[12]; const float* fW2=(const float*)d_in[13];
    const float* fb2=(const float*)d_in[14]; const float* g1=(const float*)d_in[15];
    const float* b1=(const float*)d_in[16]; const float* g2=(const float*)d_in[17];
    const float* b2=(const float*)d_in[18];
    float* out = (float*)d_out;

#define SYM(T,p,s) T p; cudaGetSymbolAddress((void**)&p, s)
    SYM(hf*,srcH,g_srcH); SYM(hf*,srcL,g_srcL); SYM(hf*,attH,g_attH);
    SYM(hf*,WqTH,g_WqTH); SYM(hf*,WqTL,g_WqTL); SYM(hf*,WkTH,g_WkTH); SYM(hf*,WkTL,g_WkTL);
    SYM(hf*,WvTH,g_WvTH);
    SYM(hf*,qH,g_qH); SYM(hf*,qL,g_qL); SYM(hf*,kH,g_kH); SYM(hf*,kL,g_kL);
    SYM(float*,v,g_v); SYM(hf*,vTH,g_vTH);
    SYM(float*,w,g_w); SYM(hf*,aH,g_aH);
    SYM(float*,ocat,g_ocat); SYM(float*,srcA,g_srcA); SYM(hf*,srcAH,g_srcAH);
    SYM(hf*,dWpTH,g_dWpTH); SYM(hf*,wpH,g_wpH);
    SYM(hf*,o2H,g_o2H); SYM(hf*,dWoTH,g_dWoTH);
    SYM(float*,o3,g_o3); SYM(float*,trgf,g_trgf); SYM(hf*,ln2H,g_ln2H);
    SYM(hf*,fW1TH,g_fW1TH); SYM(hf*,h1H,g_h1H);
    SYM(hf*,fW2TH,g_fW2TH); SYM(float*,ff,g_ff);

    cudaFuncSetAttribute(gemm_tc<1>, cudaFuncAttributeMaxDynamicSharedMemorySize, 98304);
    cudaFuncSetAttribute(gemm_tc<3>, cudaFuncAttributeMaxDynamicSharedMemorySize, 196608);
    cudaFuncSetAttribute(gemm_ff,    cudaFuncAttributeMaxDynamicSharedMemorySize, SMEMF);
    dim3 tb(32, 8);
    const long TT=(long)Tq*Tq, TD=(long)Tq*Dq, BTD=(long)BT*Dq, BTHS=(long)BT*HSq, BTT=(long)Bq*Tq*Tq;

    // operand prep
    conv_hl<<<BTD/1024, 256>>>((const float4*)src, srcH, srcL);
    conv_hl<<<BTHS/1024, 256>>>((const float4*)att, attH, nullptr);
    tconv<<<dim3(HSq/32, Dq/32, Hq), tb>>>(mWq, WqTH, WqTL, Dq, HSq);
    tconv<<<dim3(HSq/32, Dq/32, Hq), tb>>>(mWk, WkTH, WkTL, Dq, HSq);
    tconv<<<dim3(HSq/32, Dq/32, Hq), tb>>>(mWv, WvTH, nullptr, Dq, HSq);
    tconv<<<dim3(Dq/32, HSq/32, Hq), tb>>>(dWp, dWpTH, nullptr, HSq, Dq);
    tconv<<<dim3(Dq/32, Dq/32, 1), tb>>>(dWo, dWoTH, nullptr, Dq, Dq);
    tconv<<<dim3(FFq/32, Dq/32, 1), tb>>>(fW1, fW1TH, nullptr, Dq, FFq);
    tconv<<<dim3(Dq/32, FFq/32, 1), tb>>>(fW2, fW2TH, nullptr, FFq, Dq);

    // q,k (3-product: softmax amplifies score errors ~1700x), v (1-product, diluted)
    gemm_tc<3><<<dim3(4,64,Hq), 256, 196608>>>(srcH, srcL, WqTH, WqTL, mbq, nullptr, qH, qL,
        Dq, HSq, 1, 0,0, HSq,0, BTHS,0, HSq, 1.0f, 0, 0);
    gemm_tc<3><<<dim3(4,64,Hq), 256, 196608>>>(srcH, srcL, WkTH, WkTL, mbk, nullptr, kH, kL,
        Dq, HSq, 1, 0,0, HSq,0, BTHS,0, HSq, 1.0f, 0, 0);
    gemm_tc<1><<<dim3(4,64,Hq), 256, 98304>>>(srcH, nullptr, WvTH, nullptr, nullptr, v, nullptr, nullptr,
        Dq, HSq, 1, 0,0, HSq,0, BTHS,0, 0, 1.0f, 0, 0);
    tconv<<<dim3(HSq/32, Tq/32, Hq*Bq), tb>>>(v, vTH, nullptr, Tq, HSq);
    // scores: per (h,b), [1024,1024] = q @ k^T * 32 ; 3-product, causal block-skip
    gemm_tc<3><<<dim3(4,8,Hq*Bq), 256, 196608>>>(qH, qL, kH, kL, nullptr, w, nullptr, nullptr,
        HSq, Tq, Bq, BT,Tq, BT,Tq, BTT,TT, 0, 32.0f, 0, 1);
    softmax_causal<<<Hq*Bq*Tq, 256>>>(w, aH);
    // o = a @ vT^T : per (h,b); 1-product, K truncated at diagonal
    gemm_tc<1><<<dim3(4,8,Hq*Bq), 256, 98304>>>(aH, nullptr, vTH, nullptr, nullptr, ocat, nullptr, nullptr,
        Tq, Dq, Bq, Bq*Tq,Tq, Bq*HSq,HSq, (long)HSq,TD, 0, 1.0f, 0, 2);
    resln<<<BT, 256>>>(src, ocat, g1, b1, srcA, srcAH, nullptr, 0);
    // wp = att @ dWp^T : per head; 1-product (decoder chain diluted by final LN)
    gemm_tc<1><<<dim3(16,64,Hq), 256, 98304>>>(attH, nullptr, dWpTH, nullptr, dbp, nullptr, wpH, nullptr,
        HSq, Dq, 1, 0,0, Dq,0, BTD,0, Dq, 1.0f, 0, 0);
    // o2 = wp @ srcA^T : per (h,b), K=4096; 1-product
    gemm_tc<1><<<dim3(4,8,Hq*Bq), 256, 98304>>>(wpH, nullptr, srcAH, nullptr, nullptr, nullptr, o2H, nullptr,
        Dq, Dq, Bq, BT,Tq, 0,Tq, (long)Tq,TD, 0, 1.0f, 0, 0);
    // o3 = o2 @ dWo^T ; 1-product
    gemm_tc<1><<<dim3(16,64,1), 256, 98304>>>(o2H, nullptr, dWoTH, nullptr, dbo, o3, nullptr, nullptr,
        Dq, Dq, 1, 0,0, 0,0, 0,0, 0, 1.0f, 0, 0);
    resln<<<BT, 256>>>(srcA, o3, g1, b1, trgf, nullptr, nullptr, 0);
    resln<<<BT, 256>>>(trgf, nullptr, g2, b2, nullptr, ln2H, nullptr, 1);
    // h1 = gelu(ln2 @ fW1^T + fb1)  -- fp16-accumulate
    gemm_ff<<<dim3(80,64,1), 256, SMEMF>>>(ln2H, fW1TH, fb1, nullptr, h1H, Dq, FFq, 1);
    // ff = h1 @ fW2^T + fb2  -- fp16-accumulate
    gemm_ff<<<dim3(16,64,1), 256, SMEMF>>>(h1H, fW2TH, fb2, ff, nullptr, FFq, Dq, 0);
    resln<<<BT, 256>>>(trgf, ff, g2, b2, out, nullptr, nullptr, 1);
}